// round 7
// baseline (speedup 1.0000x reference)
#include <cuda_runtime.h>
#include <math.h>
#include <stdint.h>

// Problem dims
constexpr int Bb = 128, Ss = 64, Ee = 256, Hh = 256, Dd = 256, Aa = 256, Vv = 10000;
constexpr int CAT = Dd + 2*Hh + Ee;   // 1024
constexpr int RNK = Ee + 2*Hh;        // 768

// ---------------- scratch ---------------------------------------------------
constexpr size_t OFF_EMB   = 0;
constexpr size_t OFF_XPF   = OFF_EMB   + (size_t)Bb*Ss*Ee;
constexpr size_t OFF_XPB   = OFF_XPF   + (size_t)Bb*Ss*3*Hh;
constexpr size_t OFF_ENCO  = OFF_XPB   + (size_t)Bb*Ss*3*Hh;
constexpr size_t OFF_ENCP  = OFF_ENCO  + (size_t)Bb*Ss*2*Hh;
constexpr size_t OFF_HF0   = OFF_ENCP  + (size_t)Bb*Ss*Aa;
constexpr size_t OFF_HF1   = OFF_HF0   + (size_t)Bb*Hh;
constexpr size_t OFF_HB0   = OFF_HF1   + (size_t)Bb*Hh;
constexpr size_t OFF_HB1   = OFF_HB0   + (size_t)Bb*Hh;
constexpr size_t OFF_HID0  = OFF_HB1   + (size_t)Bb*Hh;
constexpr size_t OFF_HID1  = OFF_HID0  + (size_t)Bb*Dd;
constexpr size_t OFF_FCIN  = OFF_HID1  + (size_t)Bb*Dd;
constexpr size_t OFF_RNIN  = OFF_FCIN  + (size_t)Bb*2*Hh;
constexpr size_t OFF_CAT   = OFF_RNIN  + (size_t)Bb*RNK;
constexpr size_t OFF_ATTWT = OFF_CAT   + (size_t)Bb*CAT;
constexpr size_t OFF_SLOT  = OFF_ATTWT + (size_t)Dd*Aa;
constexpr size_t OFF_WHI   = OFF_SLOT  + (size_t)2*Bb;
constexpr size_t OFF_WLO   = OFF_WHI   + (size_t)Vv*CAT;
constexpr size_t SCR_TOTAL = OFF_WLO   + (size_t)Vv*CAT;

__device__ __align__(256) float g_scratch[SCR_TOTAL];

__device__ __forceinline__ float sigf(float x) { return 1.f / (1.f + expf(-x)); }

__device__ __forceinline__ unsigned int fmono(float x) {
    unsigned int b = __float_as_uint(x);
    return (b & 0x80000000u) ? ~b : (b | 0x80000000u);
}

__device__ __forceinline__ void tf32_split(float w, float& hi, float& lo) {
    unsigned int hb, lb;
    asm("cvt.rna.tf32.f32 %0, %1;" : "=r"(hb) : "f"(w));
    hi = __uint_as_float(hb);
    float res = w - hi;
    asm("cvt.rna.tf32.f32 %0, %1;" : "=r"(lb) : "f"(res));
    lo = __uint_as_float(lb);
}

#define MMA_TF32(d, A0, A1, A2, A3, B0, B1)                                      \
    asm volatile("mma.sync.aligned.m16n8k8.row.col.f32.tf32.tf32.f32 "           \
                 "{%0,%1,%2,%3}, {%4,%5,%6,%7}, {%8,%9}, {%0,%1,%2,%3};"          \
                 : "+f"(d[0]), "+f"(d[1]), "+f"(d[2]), "+f"(d[3])                 \
                 : "r"(__float_as_uint(A0)), "r"(__float_as_uint(A1)),            \
                   "r"(__float_as_uint(A2)), "r"(__float_as_uint(A3)),            \
                   "r"(__float_as_uint(B0)), "r"(__float_as_uint(B1)))

// =====================================================================
//  one-time: split out_W into tf32 hi/lo planes
// =====================================================================
__global__ void split_w_kernel(const float* __restrict__ W,
                               float* __restrict__ Whi, float* __restrict__ Wlo,
                               int total)
{
    int i = blockIdx.x * 256 + threadIdx.x;
    if (i < total) {
        float hi, lo;
        tf32_split(W[i], hi, lo);
        Whi[i] = hi; Wlo[i] = lo;
    }
}

// =====================================================================
//  gemmTC: logits GEMM via tf32 tensor cores, 3-term split.
//  C[128, Vv] = cat[128,1024] @ W[Vv,1024]^T + bias, fused argmax.
//  grid (157, 2), 128 threads (4 warps). Warp: 16 rows x 64 cols.
//  smem: (hi,lo) float2, [m][k] / [n][k], row stride 20 float2
//  (conflict-free for both STS pattern (4r+t) and frag LDS (4g+t)).
// =====================================================================
__global__ __launch_bounds__(128)
void gemmTC(const float* __restrict__ Acat,
            const float* __restrict__ Whi,
            const float* __restrict__ Wlo,
            const float* __restrict__ bias,
            float* __restrict__ C, int ldc,
            unsigned long long* __restrict__ slots)
{
    constexpr int K = CAT;
    constexpr int N = Vv;
    __shared__ __align__(16) float2 sA[64][20];
    __shared__ __align__(16) float2 sB[64][20];

    const int tid  = threadIdx.x;
    const int lane = tid & 31;
    const int warp = tid >> 5;
    const int g = lane >> 2;       // 0..7
    const int t = lane & 3;        // 0..3
    const int row0 = blockIdx.y * 64;
    const int col0 = blockIdx.x * 64;

    const int lr = tid >> 2;       // 0..31 (load row)
    const int lt = tid & 3;        // 0..3  (k sub-offset)

    float acc[8][4];
    #pragma unroll
    for (int nt = 0; nt < 8; nt++)
        #pragma unroll
        for (int q = 0; q < 4; q++) acc[nt][q] = 0.f;

    for (int k0 = 0; k0 < K; k0 += 16) {
        __syncthreads();
        #pragma unroll
        for (int h = 0; h < 2; h++) {
            const int r = lr + 32 * h;
            // A (cat): convert fp32 -> (hi,lo)
            const float* ap = Acat + (size_t)(row0 + r) * K + k0 + lt;
            #pragma unroll
            for (int e = 0; e < 4; e++) {
                float hi, lo;
                tf32_split(ap[4 * e], hi, lo);
                sA[r][lt + 4 * e] = make_float2(hi, lo);
            }
            // B (W hi/lo planes)
            const int gn = col0 + r;
            const bool v = (gn < N);
            const float* bh = Whi + (size_t)(v ? gn : 0) * K + k0 + lt;
            const float* bl = Wlo + (size_t)(v ? gn : 0) * K + k0 + lt;
            #pragma unroll
            for (int e = 0; e < 4; e++) {
                float xh = v ? bh[4 * e] : 0.f;
                float xl = v ? bl[4 * e] : 0.f;
                sB[r][lt + 4 * e] = make_float2(xh, xl);
            }
        }
        __syncthreads();

        #pragma unroll
        for (int ks = 0; ks < 16; ks += 8) {
            float2 a0 = sA[warp * 16 + g][ks + t];
            float2 a1 = sA[warp * 16 + g + 8][ks + t];
            float2 a2 = sA[warp * 16 + g][ks + t + 4];
            float2 a3 = sA[warp * 16 + g + 8][ks + t + 4];
            #pragma unroll
            for (int nt = 0; nt < 8; nt++) {
                float2 b0 = sB[nt * 8 + g][ks + t];
                float2 b1 = sB[nt * 8 + g][ks + t + 4];
                MMA_TF32(acc[nt], a0.x, a1.x, a2.x, a3.x, b0.x, b1.x);  // hi*hi
                MMA_TF32(acc[nt], a0.x, a1.x, a2.x, a3.x, b0.y, b1.y);  // hi*lo
                MMA_TF32(acc[nt], a0.y, a1.y, a2.y, a3.y, b0.x, b1.x);  // lo*hi
            }
        }
    }

    // ---- epilogue: bias, store, fused argmax ----
    const int gm0 = row0 + warp * 16 + g;
    const int gm1 = gm0 + 8;
    float best0 = -INFINITY, best1 = -INFINITY;
    int bi0 = 0, bi1 = 0;
    #pragma unroll
    for (int nt = 0; nt < 8; nt++) {
        int cb = col0 + nt * 8;
        if (cb < N) {                 // N%8==0 -> whole tile valid or not
            int c0 = cb + 2 * t;
            float b0v = bias[c0], b1v = bias[c0 + 1];
            float v00 = acc[nt][0] + b0v;
            float v01 = acc[nt][1] + b1v;
            float v10 = acc[nt][2] + b0v;
            float v11 = acc[nt][3] + b1v;
            *reinterpret_cast<float2*>(&C[(size_t)gm0 * ldc + c0]) = make_float2(v00, v01);
            *reinterpret_cast<float2*>(&C[(size_t)gm1 * ldc + c0]) = make_float2(v10, v11);
            if (v00 > best0) { best0 = v00; bi0 = c0; }
            if (v01 > best0) { best0 = v01; bi0 = c0 + 1; }
            if (v10 > best1) { best1 = v10; bi1 = c0; }
            if (v11 > best1) { best1 = v11; bi1 = c0 + 1; }
        }
    }
    unsigned long long k0p =
        ((unsigned long long)fmono(best0) << 32) |
        (unsigned long long)(0xFFFFFFFFu - (unsigned)bi0);
    unsigned long long k1p =
        ((unsigned long long)fmono(best1) << 32) |
        (unsigned long long)(0xFFFFFFFFu - (unsigned)bi1);
    #pragma unroll
    for (int o = 1; o <= 2; o <<= 1) {
        unsigned long long o0 = __shfl_xor_sync(0xffffffffu, k0p, o);
        unsigned long long o1 = __shfl_xor_sync(0xffffffffu, k1p, o);
        if (o0 > k0p) k0p = o0;
        if (o1 > k1p) k1p = o1;
    }
    if (t == 0) {
        atomicMax(&slots[gm0], k0p);
        atomicMax(&slots[gm1], k1p);
    }
}

// =====================================================================
//  gemmL: big one-time GEMMs (unchanged, passing).
// =====================================================================
__global__ __launch_bounds__(256)
void gemmL(const float* __restrict__ A, int lda,
           const float* __restrict__ Bm, int ldb,
           float* __restrict__ C, int ldc,
           const float* __restrict__ bias,
           int M, int N, int K)
{
    __shared__ __align__(16) float sA[2][16][132];
    __shared__ __align__(16) float sB[2][16][68];
    const int tid = threadIdx.x;
    const int tx = tid & 15, ty = tid >> 4;
    const int row0 = blockIdx.y * 128, col0 = blockIdx.x * 64;
    const int lr = tid >> 2;
    const int lc = (tid & 3) * 4;

    const float* Aptr0 = A + (size_t)(row0 + lr) * lda + lc;
    const float* Aptr1 = A + (size_t)(row0 + 64 + lr) * lda + lc;
    const int gnl = col0 + lr;
    const int gnc = (gnl < N) ? gnl : (N - 1);
    const float* Bptr = Bm + (size_t)gnc * ldb + lc;
    const bool bval = (gnl < N);

    float4 pa0 = *reinterpret_cast<const float4*>(Aptr0);
    float4 pa1 = *reinterpret_cast<const float4*>(Aptr1);
    float4 pb  = *reinterpret_cast<const float4*>(Bptr);
    if (!bval) pb = make_float4(0.f, 0.f, 0.f, 0.f);

    sA[0][lc+0][lr]    = pa0.x; sA[0][lc+1][lr]    = pa0.y;
    sA[0][lc+2][lr]    = pa0.z; sA[0][lc+3][lr]    = pa0.w;
    sA[0][lc+0][64+lr] = pa1.x; sA[0][lc+1][64+lr] = pa1.y;
    sA[0][lc+2][64+lr] = pa1.z; sA[0][lc+3][64+lr] = pa1.w;
    sB[0][lc+0][lr] = pb.x; sB[0][lc+1][lr] = pb.y;
    sB[0][lc+2][lr] = pb.z; sB[0][lc+3][lr] = pb.w;
    __syncthreads();

    float acc[8][4];
    #pragma unroll
    for (int i = 0; i < 8; i++)
        #pragma unroll
        for (int j = 0; j < 4; j++) acc[i][j] = 0.f;

    int buf = 0;
    for (int k0 = 16; k0 <= K; k0 += 16) {
        const bool has_next = (k0 < K);
        if (has_next) {
            pa0 = *reinterpret_cast<const float4*>(Aptr0 + k0);
            pa1 = *reinterpret_cast<const float4*>(Aptr1 + k0);
            pb  = *reinterpret_cast<const float4*>(Bptr + k0);
            if (!bval) pb = make_float4(0.f, 0.f, 0.f, 0.f);
        }
        #pragma unroll
        for (int kk = 0; kk < 16; kk++) {
            float4 av0 = *reinterpret_cast<const float4*>(&sA[buf][kk][ty*8]);
            float4 av1 = *reinterpret_cast<const float4*>(&sA[buf][kk][ty*8+4]);
            float4 bv  = *reinterpret_cast<const float4*>(&sB[buf][kk][tx*4]);
            float a[8] = {av0.x, av0.y, av0.z, av0.w, av1.x, av1.y, av1.z, av1.w};
            float b[4] = {bv.x, bv.y, bv.z, bv.w};
            #pragma unroll
            for (int i = 0; i < 8; i++)
                #pragma unroll
                for (int j = 0; j < 4; j++) acc[i][j] += a[i] * b[j];
        }
        if (has_next) {
            const int nb = buf ^ 1;
            sA[nb][lc+0][lr]    = pa0.x; sA[nb][lc+1][lr]    = pa0.y;
            sA[nb][lc+2][lr]    = pa0.z; sA[nb][lc+3][lr]    = pa0.w;
            sA[nb][lc+0][64+lr] = pa1.x; sA[nb][lc+1][64+lr] = pa1.y;
            sA[nb][lc+2][64+lr] = pa1.z; sA[nb][lc+3][64+lr] = pa1.w;
            sB[nb][lc+0][lr] = pb.x; sB[nb][lc+1][lr] = pb.y;
            sB[nb][lc+2][lr] = pb.z; sB[nb][lc+3][lr] = pb.w;
            __syncthreads();
            buf = nb;
        }
    }

    #pragma unroll
    for (int i = 0; i < 8; i++) {
        const int gm = row0 + ty*8 + i;
        #pragma unroll
        for (int j = 0; j < 4; j++) {
            int gn = col0 + tx*4 + j;
            if (gn < N)
                C[(size_t)gm * ldc + gn] = acc[i][j] + (bias ? bias[gn] : 0.f);
        }
    }
}

// ---------------- small generic GEMM (decoder init only) -------------------
__global__ void gemm32t(const float* __restrict__ A, int lda,
                        const float* __restrict__ Bm, int ldb,
                        float* __restrict__ C, int ldc,
                        const float* __restrict__ bias,
                        int M, int N, int K)
{
    __shared__ float sA[32][33];
    __shared__ float sB[32][33];
    const int tid = threadIdx.x;
    const int tx = tid & 15, ty = tid >> 4;
    const int row0 = blockIdx.y * 32, col0 = blockIdx.x * 32;

    float acc[2][2] = {{0,0},{0,0}};
    for (int k0 = 0; k0 < K; k0 += 32) {
        #pragma unroll
        for (int i = tid; i < 1024; i += 256) {
            int m = i >> 5, kk = i & 31;
            sA[kk][m] = A[(size_t)(row0 + m) * lda + k0 + kk];
            sB[kk][m] = Bm[(size_t)(col0 + m) * ldb + k0 + kk];
        }
        __syncthreads();
        #pragma unroll
        for (int kk = 0; kk < 32; kk++) {
            float a0 = sA[kk][ty*2], a1 = sA[kk][ty*2+1];
            float b0 = sB[kk][tx*2], b1 = sB[kk][tx*2+1];
            acc[0][0] += a0*b0; acc[0][1] += a0*b1;
            acc[1][0] += a1*b0; acc[1][1] += a1*b1;
        }
        __syncthreads();
    }
    #pragma unroll
    for (int i = 0; i < 2; i++)
        #pragma unroll
        for (int j = 0; j < 2; j++) {
            int gm = row0 + ty*2 + i, gn = col0 + tx*2 + j;
            C[(size_t)gm * ldc + gn] = tanhf(acc[i][j] + bias[gn]);
        }
}

// =====================================================================
//  Encoder fused step
// =====================================================================
__global__ __launch_bounds__(256)
void enc_step_kernel(const float* __restrict__ hf_in,  const float* __restrict__ hb_in,
                     float* __restrict__ hf_out, float* __restrict__ hb_out,
                     const float* __restrict__ Whh_f, const float* __restrict__ Whh_b,
                     const float* __restrict__ bhh_f, const float* __restrict__ bhh_b,
                     const float* __restrict__ xpf,   const float* __restrict__ xpb,
                     float* __restrict__ enc_out, int t)
{
    const int dir = blockIdx.z;
    const float* hin  = dir ? hb_in  : hf_in;
    const float* Whh  = dir ? Whh_b  : Whh_f;
    const float* bhh  = dir ? bhh_b  : bhh_f;
    const float* xp   = dir ? xpb    : xpf;
    float*       hout = dir ? hb_out : hf_out;
    const int s = dir ? (Ss - 1 - t) : t;

    const int j0 = blockIdx.x * 32, b0 = blockIdx.y * 32;
    const int tid = threadIdx.x;
    const int tx = tid & 15, ty = tid >> 4;

    __shared__ float sH[16][33];
    __shared__ float sW[3][16][34];

    float acc[2][2][3];
    #pragma unroll
    for (int bi = 0; bi < 2; bi++)
        #pragma unroll
        for (int ji = 0; ji < 2; ji++)
            #pragma unroll
            for (int g = 0; g < 3; g++) acc[bi][ji][g] = 0.f;

    for (int k0 = 0; k0 < Hh; k0 += 16) {
        #pragma unroll
        for (int i = tid; i < 512; i += 256) {
            int b = i >> 4, kk = i & 15;
            sH[kk][b] = hin[(size_t)(b0 + b) * Hh + k0 + kk];
        }
        #pragma unroll
        for (int i = tid; i < 1536; i += 256) {
            int r = i >> 4, kk = i & 15;
            int g = r / 32, j = r % 32;
            sW[g][kk][j] = Whh[(size_t)(g * Hh + j0 + j) * Hh + k0 + kk];
        }
        __syncthreads();
        #pragma unroll
        for (int kk = 0; kk < 16; kk++) {
            float hv[2] = { sH[kk][ty*2], sH[kk][ty*2 + 1] };
            #pragma unroll
            for (int g = 0; g < 3; g++) {
                float w0 = sW[g][kk][tx*2], w1 = sW[g][kk][tx*2 + 1];
                acc[0][0][g] += hv[0] * w0;
                acc[0][1][g] += hv[0] * w1;
                acc[1][0][g] += hv[1] * w0;
                acc[1][1][g] += hv[1] * w1;
            }
        }
        __syncthreads();
    }

    #pragma unroll
    for (int bi = 0; bi < 2; bi++) {
        int b = b0 + ty*2 + bi;
        #pragma unroll
        for (int ji = 0; ji < 2; ji++) {
            int j = j0 + tx*2 + ji;
            float rh = acc[bi][ji][0] + bhh[j];
            float zh = acc[bi][ji][1] + bhh[Hh + j];
            float nh = acc[bi][ji][2] + bhh[2*Hh + j];
            const float* x = xp + ((size_t)b * Ss + s) * (3*Hh);
            float r = sigf(x[j] + rh);
            float z = sigf(x[Hh + j] + zh);
            float n = tanhf(x[2*Hh + j] + r * nh);
            float hv = hin[(size_t)b * Hh + j];
            float hn = (1.f - z) * n + z * hv;
            hout[(size_t)b * Hh + j] = hn;
            enc_out[((size_t)b * Ss + s) * (2*Hh) + dir * Hh + j] = hn;
        }
    }
}

// =====================================================================
//  Decoder fused GRU step
// =====================================================================
__global__ __launch_bounds__(256)
void dec_fused_kernel(const float* __restrict__ rnin,
                      const float* __restrict__ hid_in,
                      const float* __restrict__ dec_Wih,
                      const float* __restrict__ dec_Whh,
                      const float* __restrict__ dec_bih,
                      const float* __restrict__ dec_bhh,
                      float* __restrict__ hid_out, float* __restrict__ cat,
                      unsigned long long* __restrict__ slots)
{
    const int j0 = blockIdx.x * 32, b0 = blockIdx.y * 32;
    const int tid = threadIdx.x;
    const int tx = tid & 15, ty = tid >> 4;

    __shared__ float sH[16][33];
    __shared__ float sW[4][16][34];

    float acc[2][2][4];
    #pragma unroll
    for (int bi = 0; bi < 2; bi++)
        #pragma unroll
        for (int ji = 0; ji < 2; ji++)
            #pragma unroll
            for (int g = 0; g < 4; g++) acc[bi][ji][g] = 0.f;

    for (int k0 = 0; k0 < RNK + Dd; k0 += 16) {
        const bool ih = (k0 < RNK);
        #pragma unroll
        for (int i = tid; i < 512; i += 256) {
            int b = i >> 4, kk = i & 15;
            sH[kk][b] = ih ? rnin[(size_t)(b0 + b) * RNK + k0 + kk]
                           : hid_in[(size_t)(b0 + b) * Dd + (k0 - RNK) + kk];
        }
        #pragma unroll
        for (int i = tid; i < 2048; i += 256) {
            int g = i >> 9;
            int r = (i >> 4) & 31;
            int kk = i & 15;
            int j = j0 + r;
            float w;
            if (ih) {
                w = (g == 3) ? 0.f
                    : dec_Wih[(size_t)(g * Dd + j) * RNK + k0 + kk];
            } else {
                w = (g == 2) ? 0.f
                    : dec_Whh[(size_t)(((g == 3) ? 2 : g) * Dd + j) * Dd + (k0 - RNK) + kk];
            }
            sW[g][kk][r] = w;
        }
        __syncthreads();
        #pragma unroll
        for (int kk = 0; kk < 16; kk++) {
            float hv0 = sH[kk][ty*2], hv1 = sH[kk][ty*2 + 1];
            #pragma unroll
            for (int g = 0; g < 4; g++) {
                float w0 = sW[g][kk][tx*2], w1 = sW[g][kk][tx*2 + 1];
                acc[0][0][g] += hv0 * w0;
                acc[0][1][g] += hv0 * w1;
                acc[1][0][g] += hv1 * w0;
                acc[1][1][g] += hv1 * w1;
            }
        }
        __syncthreads();
    }

    #pragma unroll
    for (int bi = 0; bi < 2; bi++) {
        int b = b0 + ty*2 + bi;
        #pragma unroll
        for (int ji = 0; ji < 2; ji++) {
            int j = j0 + tx*2 + ji;
            float r = sigf(acc[bi][ji][0] + dec_bih[j] + dec_bhh[j]);
            float z = sigf(acc[bi][ji][1] + dec_bih[Dd + j] + dec_bhh[Dd + j]);
            float n = tanhf(acc[bi][ji][2] + dec_bih[2*Dd + j]
                            + r * (acc[bi][ji][3] + dec_bhh[2*Dd + j]));
            float hv = hid_in[(size_t)b * Dd + j];
            float hn = (1.f - z) * n + z * hv;
            hid_out[(size_t)b * Dd + j] = hn;
            cat[(size_t)b * CAT + j] = hn;
            if (j == 0) slots[b] = 0ull;
        }
    }
}

// ---------------- small helper kernels ------------------------------------
__global__ void init0_kernel(float* hf, float* hb, unsigned long long* slots)
{
    int i = blockIdx.x * 256 + threadIdx.x;
    if (i < Bb * Hh) { hf[i] = 0.f; hb[i] = 0.f; }
    if (i < Bb)
        slots[i] = ((unsigned long long)fmono(0.f) << 32) | 0xFFFFFFFFull;
}

__global__ void embed_kernel(const int* __restrict__ inp,
                             const float* __restrict__ tab,
                             float* __restrict__ emb)
{
    int bs = blockIdx.x, j = threadIdx.x;
    int tk = inp[bs * 2 + 0];
    float m = (float)inp[bs * 2 + 1];
    emb[(size_t)bs * Ee + j] = tab[(size_t)tk * Ee + j] * m;
}

__global__ void transpose_attw_kernel(const float* __restrict__ attn_W,
                                      float* __restrict__ attWT)
{
    int k = blockIdx.x, j = threadIdx.x;
    attWT[(size_t)k * Aa + j] = attn_W[(size_t)j * (Dd + 2*Hh) + k];
}

__global__ void concat_fc_kernel(const float* __restrict__ hf,
                                 const float* __restrict__ hb,
                                 float* __restrict__ fcin)
{
    int b = blockIdx.x, j = threadIdx.x;
    fcin[(size_t)b*2*Hh + j]      = hf[(size_t)b*Hh + j];
    fcin[(size_t)b*2*Hh + Hh + j] = hb[(size_t)b*Hh + j];
}

// attention (with fused hproj) + decoder-token embedding
__global__ __launch_bounds__(256)
void attn_embed_kernel(const float* __restrict__ encp,
                       const float* __restrict__ hid,
                       const float* __restrict__ attWT,
                       const float* __restrict__ enc_out,
                       const unsigned long long* __restrict__ slots,
                       const float* __restrict__ tab,
                       float* __restrict__ rnin, float* __restrict__ cat)
{
    int b = blockIdx.x, tid = threadIdx.x;
    int lane = tid & 31, w = tid >> 5;
    __shared__ float shid[Dd];
    __shared__ float shp[Aa];
    __shared__ float salpha[Ss];

    shid[tid] = hid[(size_t)b*Dd + tid];
    __syncthreads();

    float hp = 0.f;
    #pragma unroll 8
    for (int k = 0; k < Dd; k++) hp += shid[k] * attWT[(size_t)k * Aa + tid];
    shp[tid] = hp;
    __syncthreads();

    #pragma unroll
    for (int i = 0; i < 8; i++) {
        int s = w + 8 * i;
        const float* row = encp + ((size_t)b*Ss + s)*Aa;
        float acc = 0.f;
        #pragma unroll
        for (int a = lane; a < Aa; a += 32) acc += tanhf(row[a] + shp[a]);
        #pragma unroll
        for (int o = 16; o; o >>= 1) acc += __shfl_xor_sync(0xffffffffu, acc, o);
        if (lane == 0) salpha[s] = acc;
    }
    __syncthreads();
    if (w == 0) {
        float v0 = salpha[lane], v1 = salpha[lane + 32];
        float m = fmaxf(v0, v1);
        #pragma unroll
        for (int o = 16; o; o >>= 1) m = fmaxf(m, __shfl_xor_sync(0xffffffffu, m, o));
        float e0 = expf(v0 - m), e1 = expf(v1 - m);
        float sum = e0 + e1;
        #pragma unroll
        for (int o = 16; o; o >>= 1) sum += __shfl_xor_sync(0xffffffffu, sum, o);
        float inv = 1.f / sum;
        salpha[lane] = e0 * inv; salpha[lane + 32] = e1 * inv;
    }
    __syncthreads();
    float a0 = 0.f, a1 = 0.f;
    for (int s = 0; s < Ss; s++) {
        float al = salpha[s];
        const float* eo = enc_out + ((size_t)b*Ss + s)*(2*Hh);
        a0 += al * eo[tid];
        a1 += al * eo[Hh + tid];
    }
    rnin[(size_t)b*RNK + Ee + tid]      = a0;
    rnin[(size_t)b*RNK + Ee + Hh + tid] = a1;
    cat[(size_t)b*CAT + Dd + tid]       = a0;
    cat[(size_t)b*CAT + Dd + Hh + tid]  = a1;

    int tk = (int)(0xFFFFFFFFu - (unsigned)(slots[b] & 0xFFFFFFFFull));
    float e = tab[(size_t)tk * Ee + tid];
    rnin[(size_t)b*RNK + tid] = e;
    cat[(size_t)b*CAT + Dd + 2*Hh + tid] = e;
}

__global__ void logsoftmax_kernel(float* __restrict__ out)
{
    int row = blockIdx.x, tid = threadIdx.x;
    int s = row & (Ss - 1);
    float* p = out + (size_t)row * Vv;
    if (s == 0) {
        float L = logf(expf(1.f) + (float)(Vv - 1));
        for (int v = tid; v < Vv; v += 256) p[v] = (v == 0 ? 1.f : 0.f) - L;
        return;
    }
    constexpr int PT = (Vv + 255) / 256;
    float regs[PT];
    float m = -INFINITY;
    #pragma unroll
    for (int i = 0; i < PT; i++) {
        int v = tid + i * 256;
        if (v < Vv) { regs[i] = p[v]; m = fmaxf(m, regs[i]); }
        else regs[i] = -INFINITY;
    }
    __shared__ float sm[256];
    sm[tid] = m; __syncthreads();
    for (int o = 128; o; o >>= 1) { if (tid < o) sm[tid] = fmaxf(sm[tid], sm[tid+o]); __syncthreads(); }
    m = sm[0]; __syncthreads();
    float sum = 0.f;
    #pragma unroll
    for (int i = 0; i < PT; i++) {
        int v = tid + i * 256;
        if (v < Vv) sum += expf(regs[i] - m);
    }
    sm[tid] = sum; __syncthreads();
    for (int o = 128; o; o >>= 1) { if (tid < o) sm[tid] += sm[tid+o]; __syncthreads(); }
    float ls = m + logf(sm[0]);
    #pragma unroll
    for (int i = 0; i < PT; i++) {
        int v = tid + i * 256;
        if (v < Vv) p[v] = regs[i] - ls;
    }
}

// ---------------- launch helpers ------------------------------------------
static inline dim3 gridL(int M, int N) { return dim3((N + 63) / 64, M / 128); }

extern "C" void kernel_launch(void* const* d_in, const int* in_sizes, int n_in,
                              void* d_out, int out_size)
{
    const int*   inp       = (const int*)  d_in[0];
    const float* emb_table = (const float*)d_in[1];
    const float* Wih_f     = (const float*)d_in[2];
    const float* Whh_f     = (const float*)d_in[3];
    const float* bih_f     = (const float*)d_in[4];
    const float* bhh_f     = (const float*)d_in[5];
    const float* Wih_b     = (const float*)d_in[6];
    const float* Whh_b     = (const float*)d_in[7];
    const float* bih_b     = (const float*)d_in[8];
    const float* bhh_b     = (const float*)d_in[9];
    const float* fc_W      = (const float*)d_in[10];
    const float* fc_b      = (const float*)d_in[11];
    const float* attn_W    = (const float*)d_in[12];
    const float* attn_b    = (const float*)d_in[13];
    const float* dec_Wih   = (const float*)d_in[14];
    const float* dec_Whh   = (const float*)d_in[15];
    const float* dec_bih   = (const float*)d_in[16];
    const float* dec_bhh   = (const float*)d_in[17];
    const float* out_W     = (const float*)d_in[18];
    const float* out_b     = (const float*)d_in[19];
    float* out = (float*)d_out;

    float* scr = nullptr;
    cudaGetSymbolAddress((void**)&scr, g_scratch);
    float* emb   = scr + OFF_EMB;
    float* xpf   = scr + OFF_XPF;
    float* xpb   = scr + OFF_XPB;
    float* enco  = scr + OFF_ENCO;
    float* encp  = scr + OFF_ENCP;
    float* hf0   = scr + OFF_HF0;
    float* hf1   = scr + OFF_HF1;
    float* hb0   = scr + OFF_HB0;
    float* hb1   = scr + OFF_HB1;
    float* hid0  = scr + OFF_HID0;
    float* hid1  = scr + OFF_HID1;
    float* fcin  = scr + OFF_FCIN;
    float* rnin  = scr + OFF_RNIN;
    float* cat   = scr + OFF_CAT;
    float* attWT = scr + OFF_ATTWT;
    float* Whi   = scr + OFF_WHI;
    float* Wlo   = scr + OFF_WLO;
    unsigned long long* slots = (unsigned long long*)(scr + OFF_SLOT);

    // ---- init + embedding + one-time GEMMs + weight split ----
    init0_kernel<<<(Bb*Hh + 255)/256, 256>>>(hf0, hb0, slots);
    embed_kernel<<<Bb*Ss, 256>>>(inp, emb_table, emb);
    transpose_attw_kernel<<<Dd, Aa>>>(attn_W, attWT);
    split_w_kernel<<<(Vv*CAT + 255)/256, 256>>>(out_W, Whi, Wlo, Vv*CAT);
    gemmL<<<gridL(Bb*Ss, 3*Hh), 256>>>(emb, Ee, Wih_f, Ee, xpf, 3*Hh, bih_f, Bb*Ss, 3*Hh, Ee);
    gemmL<<<gridL(Bb*Ss, 3*Hh), 256>>>(emb, Ee, Wih_b, Ee, xpb, 3*Hh, bih_b, Bb*Ss, 3*Hh, Ee);

    // ---- encoder recurrence ----
    for (int t = 0; t < Ss; t++) {
        const float* hfi = (t & 1) ? hf1 : hf0;
        const float* hbi = (t & 1) ? hb1 : hb0;
        float* hfo = (t & 1) ? hf0 : hf1;
        float* hbo = (t & 1) ? hb0 : hb1;
        enc_step_kernel<<<dim3(8, 4, 2), 256>>>(hfi, hbi, hfo, hbo,
                                                Whh_f, Whh_b, bhh_f, bhh_b,
                                                xpf, xpb, enco, t);
    }

    // ---- decoder init ----
    concat_fc_kernel<<<Bb, 256>>>(hf0, hb0, fcin);
    gemm32t<<<dim3(Dd/32, Bb/32), 256>>>(fcin, 2*Hh, fc_W, 2*Hh, hid0, Dd, fc_b, Bb, Dd, 2*Hh);

    // ---- attention projection of enc_out (one-time) ----
    gemmL<<<gridL(Bb*Ss, Aa), 256>>>(enco, 2*Hh, attn_W + Dd, Dd + 2*Hh, encp, Aa, attn_b, Bb*Ss, Aa, 2*Hh);

    // ---- decoder steps (3 launches each) ----
    const dim3 gTC((Vv + 63) / 64, Bb / 64);
    for (int t = 0; t < Ss - 1; t++) {
        const float* hin = (t & 1) ? hid1 : hid0;
        float*       hout = (t & 1) ? hid0 : hid1;
        attn_embed_kernel<<<Bb, 256>>>(encp, hin, attWT, enco, slots, emb_table, rnin, cat);
        dec_fused_kernel<<<dim3(8, 4), 256>>>(rnin, hin, dec_Wih, dec_Whh,
                                              dec_bih, dec_bhh, hout, cat, slots);
        gemmTC<<<gTC, 128>>>(cat, Whi, Wlo, out_b,
                             out + (size_t)(t + 1) * Vv, Ss * Vv, slots);
    }

    // ---- final log-softmax ----
    logsoftmax_kernel<<<Bb*Ss, 256>>>(out);
}

// round 8
// speedup vs baseline: 1.1686x; 1.1686x over previous
#include <cuda_runtime.h>
#include <math.h>
#include <stdint.h>

// Problem dims
constexpr int Bb = 128, Ss = 64, Ee = 256, Hh = 256, Dd = 256, Aa = 256, Vv = 10000;
constexpr int CAT = Dd + 2*Hh + Ee;   // 1024
constexpr int RNK = Ee + 2*Hh;        // 768

// ---------------- scratch ---------------------------------------------------
constexpr size_t OFF_EMB   = 0;
constexpr size_t OFF_XPF   = OFF_EMB   + (size_t)Bb*Ss*Ee;
constexpr size_t OFF_XPB   = OFF_XPF   + (size_t)Bb*Ss*3*Hh;
constexpr size_t OFF_ENCO  = OFF_XPB   + (size_t)Bb*Ss*3*Hh;
constexpr size_t OFF_ENCP  = OFF_ENCO  + (size_t)Bb*Ss*2*Hh;
constexpr size_t OFF_HF0   = OFF_ENCP  + (size_t)Bb*Ss*Aa;
constexpr size_t OFF_HF1   = OFF_HF0   + (size_t)Bb*Hh;
constexpr size_t OFF_HB0   = OFF_HF1   + (size_t)Bb*Hh;
constexpr size_t OFF_HB1   = OFF_HB0   + (size_t)Bb*Hh;
constexpr size_t OFF_HID0  = OFF_HB1   + (size_t)Bb*Hh;
constexpr size_t OFF_HID1  = OFF_HID0  + (size_t)Bb*Dd;
constexpr size_t OFF_FCIN  = OFF_HID1  + (size_t)Bb*Dd;
constexpr size_t OFF_RNIN  = OFF_FCIN  + (size_t)Bb*2*Hh;
constexpr size_t OFF_ATTWT = OFF_RNIN  + (size_t)Bb*RNK;
constexpr size_t OFF_SLOT  = OFF_ATTWT + (size_t)Dd*Aa;
constexpr size_t OFF_CATHL = OFF_SLOT  + (size_t)2*Bb;           // float2 [Bb][CAT]
constexpr size_t OFF_WHL   = OFF_CATHL + (size_t)2*Bb*CAT;       // float2 [Vv][CAT]
constexpr size_t SCR_TOTAL = OFF_WHL   + (size_t)2*Vv*CAT;

__device__ __align__(256) float g_scratch[SCR_TOTAL];

__device__ __forceinline__ float sigf(float x) { return 1.f / (1.f + expf(-x)); }

__device__ __forceinline__ unsigned int fmono(float x) {
    unsigned int b = __float_as_uint(x);
    return (b & 0x80000000u) ? ~b : (b | 0x80000000u);
}

__device__ __forceinline__ float2 tf32_split2(float w) {
    unsigned int hb, lb;
    asm("cvt.rna.tf32.f32 %0, %1;" : "=r"(hb) : "f"(w));
    float hi = __uint_as_float(hb);
    float res = w - hi;
    asm("cvt.rna.tf32.f32 %0, %1;" : "=r"(lb) : "f"(res));
    return make_float2(hi, __uint_as_float(lb));
}

#define MMA_TF32(d, A0, A1, A2, A3, B0, B1)                                      \
    asm volatile("mma.sync.aligned.m16n8k8.row.col.f32.tf32.tf32.f32 "           \
                 "{%0,%1,%2,%3}, {%4,%5,%6,%7}, {%8,%9}, {%0,%1,%2,%3};"          \
                 : "+f"(d[0]), "+f"(d[1]), "+f"(d[2]), "+f"(d[3])                 \
                 : "r"(__float_as_uint(A0)), "r"(__float_as_uint(A1)),            \
                   "r"(__float_as_uint(A2)), "r"(__float_as_uint(A3)),            \
                   "r"(__float_as_uint(B0)), "r"(__float_as_uint(B1)))

// =====================================================================
//  one-time: split out_W into interleaved (hi,lo) float2 plane
// =====================================================================
__global__ void split_w_kernel(const float* __restrict__ W,
                               float2* __restrict__ WHL, int total)
{
    int i = blockIdx.x * 256 + threadIdx.x;
    if (i < total) WHL[i] = tf32_split2(W[i]);
}

// =====================================================================
//  gemmTC2: logits GEMM via tf32 mma.sync, 3-term split, pre-split inputs.
//  C[128, Vv] = cat[128,1024] @ W[Vv,1024]^T + bias, fused argmax.
//  grid (157, 2), 256 threads (8 warps = 4 m-tiles x 2 n-halves).
//  BM=64, BN=64, BK=16, double-buffered, float4 global loads.
// =====================================================================
__global__ __launch_bounds__(256)
void gemmTC2(const float2* __restrict__ AHL,
             const float2* __restrict__ WHL,
             const float* __restrict__ bias,
             float* __restrict__ C, int ldc,
             unsigned long long* __restrict__ slots)
{
    constexpr int K = CAT;
    constexpr int N = Vv;
    constexpr int NCH = K / 16;          // 64 chunks
    __shared__ __align__(16) float2 sA[2][64][20];
    __shared__ __align__(16) float2 sB[2][64][20];

    const int tid  = threadIdx.x;
    const int lane = tid & 31;
    const int warp = tid >> 5;
    const int wm = warp & 3;             // m tile (16 rows)
    const int wn = warp >> 2;            // n half (32 cols)
    const int g = lane >> 2;             // 0..7
    const int t = lane & 3;              // 0..3
    const int row0 = blockIdx.y * 64;
    const int col0 = blockIdx.x * 64;

    // cooperative load: each thread loads 2 float4 (=4 float2) per tensor/chunk
    const int lr  = tid >> 2;            // 0..63
    const int lc2 = (tid & 3) * 4;       // float2 col base: 0,4,8,12

    const float4* Ap = reinterpret_cast<const float4*>(AHL + (size_t)(row0 + lr) * K + lc2);
    const int gn = col0 + lr;
    const bool bv = (gn < N);
    const float4* Bp = reinterpret_cast<const float4*>(WHL + (size_t)(bv ? gn : 0) * K + lc2);
    const float4 z4 = make_float4(0.f, 0.f, 0.f, 0.f);

    // preload chunk 0
    float4 a0r = Ap[0], a1r = Ap[1];
    float4 b0r = bv ? Bp[0] : z4, b1r = bv ? Bp[1] : z4;
    *reinterpret_cast<float4*>(&sA[0][lr][lc2])     = a0r;
    *reinterpret_cast<float4*>(&sA[0][lr][lc2 + 2]) = a1r;
    *reinterpret_cast<float4*>(&sB[0][lr][lc2])     = b0r;
    *reinterpret_cast<float4*>(&sB[0][lr][lc2 + 2]) = b1r;
    __syncthreads();

    float acc[4][4];
    #pragma unroll
    for (int nt = 0; nt < 4; nt++)
        #pragma unroll
        for (int q = 0; q < 4; q++) acc[nt][q] = 0.f;

    int buf = 0;
    for (int ci = 0; ci < NCH; ci++) {
        const bool has_next = (ci + 1 < NCH);
        if (has_next) {
            const int f4 = (ci + 1) * 8;
            a0r = Ap[f4]; a1r = Ap[f4 + 1];
            b0r = bv ? Bp[f4] : z4; b1r = bv ? Bp[f4 + 1] : z4;
        }
        #pragma unroll
        for (int ks = 0; ks < 16; ks += 8) {
            float2 A0 = sA[buf][wm*16 + g][ks + t];
            float2 A1 = sA[buf][wm*16 + g + 8][ks + t];
            float2 A2 = sA[buf][wm*16 + g][ks + t + 4];
            float2 A3 = sA[buf][wm*16 + g + 8][ks + t + 4];
            #pragma unroll
            for (int nt = 0; nt < 4; nt++) {
                float2 B0 = sB[buf][wn*32 + nt*8 + g][ks + t];
                float2 B1 = sB[buf][wn*32 + nt*8 + g][ks + t + 4];
                MMA_TF32(acc[nt], A0.x, A1.x, A2.x, A3.x, B0.x, B1.x);  // hi*hi
                MMA_TF32(acc[nt], A0.x, A1.x, A2.x, A3.x, B0.y, B1.y);  // hi*lo
                MMA_TF32(acc[nt], A0.y, A1.y, A2.y, A3.y, B0.x, B1.x);  // lo*hi
            }
        }
        if (has_next) {
            const int nb = buf ^ 1;
            *reinterpret_cast<float4*>(&sA[nb][lr][lc2])     = a0r;
            *reinterpret_cast<float4*>(&sA[nb][lr][lc2 + 2]) = a1r;
            *reinterpret_cast<float4*>(&sB[nb][lr][lc2])     = b0r;
            *reinterpret_cast<float4*>(&sB[nb][lr][lc2 + 2]) = b1r;
            __syncthreads();
            buf = nb;
        }
    }

    // ---- epilogue: bias, store, fused argmax ----
    const int gm0 = row0 + wm*16 + g;
    const int gm1 = gm0 + 8;
    float best0 = -INFINITY, best1 = -INFINITY;
    int bi0 = 0, bi1 = 0;
    #pragma unroll
    for (int nt = 0; nt < 4; nt++) {
        const int cb = col0 + wn*32 + nt*8;
        if (cb < N) {                    // N%8==0 -> tile fully valid or not
            const int c0 = cb + 2*t;
            float bv0 = bias[c0], bv1 = bias[c0 + 1];
            float v00 = acc[nt][0] + bv0;
            float v01 = acc[nt][1] + bv1;
            float v10 = acc[nt][2] + bv0;
            float v11 = acc[nt][3] + bv1;
            *reinterpret_cast<float2*>(&C[(size_t)gm0 * ldc + c0]) = make_float2(v00, v01);
            *reinterpret_cast<float2*>(&C[(size_t)gm1 * ldc + c0]) = make_float2(v10, v11);
            if (v00 > best0) { best0 = v00; bi0 = c0; }
            if (v01 > best0) { best0 = v01; bi0 = c0 + 1; }
            if (v10 > best1) { best1 = v10; bi1 = c0; }
            if (v11 > best1) { best1 = v11; bi1 = c0 + 1; }
        }
    }
    unsigned long long k0p =
        ((unsigned long long)fmono(best0) << 32) |
        (unsigned long long)(0xFFFFFFFFu - (unsigned)bi0);
    unsigned long long k1p =
        ((unsigned long long)fmono(best1) << 32) |
        (unsigned long long)(0xFFFFFFFFu - (unsigned)bi1);
    #pragma unroll
    for (int o = 1; o <= 2; o <<= 1) {
        unsigned long long o0 = __shfl_xor_sync(0xffffffffu, k0p, o);
        unsigned long long o1 = __shfl_xor_sync(0xffffffffu, k1p, o);
        if (o0 > k0p) k0p = o0;
        if (o1 > k1p) k1p = o1;
    }
    if (t == 0) {
        atomicMax(&slots[gm0], k0p);
        atomicMax(&slots[gm1], k1p);
    }
}

// =====================================================================
//  gemmL: big one-time GEMMs (unchanged, passing).
// =====================================================================
__global__ __launch_bounds__(256)
void gemmL(const float* __restrict__ A, int lda,
           const float* __restrict__ Bm, int ldb,
           float* __restrict__ C, int ldc,
           const float* __restrict__ bias,
           int M, int N, int K)
{
    __shared__ __align__(16) float sA[2][16][132];
    __shared__ __align__(16) float sB[2][16][68];
    const int tid = threadIdx.x;
    const int tx = tid & 15, ty = tid >> 4;
    const int row0 = blockIdx.y * 128, col0 = blockIdx.x * 64;
    const int lr = tid >> 2;
    const int lc = (tid & 3) * 4;

    const float* Aptr0 = A + (size_t)(row0 + lr) * lda + lc;
    const float* Aptr1 = A + (size_t)(row0 + 64 + lr) * lda + lc;
    const int gnl = col0 + lr;
    const int gnc = (gnl < N) ? gnl : (N - 1);
    const float* Bptr = Bm + (size_t)gnc * ldb + lc;
    const bool bval = (gnl < N);

    float4 pa0 = *reinterpret_cast<const float4*>(Aptr0);
    float4 pa1 = *reinterpret_cast<const float4*>(Aptr1);
    float4 pb  = *reinterpret_cast<const float4*>(Bptr);
    if (!bval) pb = make_float4(0.f, 0.f, 0.f, 0.f);

    sA[0][lc+0][lr]    = pa0.x; sA[0][lc+1][lr]    = pa0.y;
    sA[0][lc+2][lr]    = pa0.z; sA[0][lc+3][lr]    = pa0.w;
    sA[0][lc+0][64+lr] = pa1.x; sA[0][lc+1][64+lr] = pa1.y;
    sA[0][lc+2][64+lr] = pa1.z; sA[0][lc+3][64+lr] = pa1.w;
    sB[0][lc+0][lr] = pb.x; sB[0][lc+1][lr] = pb.y;
    sB[0][lc+2][lr] = pb.z; sB[0][lc+3][lr] = pb.w;
    __syncthreads();

    float acc[8][4];
    #pragma unroll
    for (int i = 0; i < 8; i++)
        #pragma unroll
        for (int j = 0; j < 4; j++) acc[i][j] = 0.f;

    int buf = 0;
    for (int k0 = 16; k0 <= K; k0 += 16) {
        const bool has_next = (k0 < K);
        if (has_next) {
            pa0 = *reinterpret_cast<const float4*>(Aptr0 + k0);
            pa1 = *reinterpret_cast<const float4*>(Aptr1 + k0);
            pb  = *reinterpret_cast<const float4*>(Bptr + k0);
            if (!bval) pb = make_float4(0.f, 0.f, 0.f, 0.f);
        }
        #pragma unroll
        for (int kk = 0; kk < 16; kk++) {
            float4 av0 = *reinterpret_cast<const float4*>(&sA[buf][kk][ty*8]);
            float4 av1 = *reinterpret_cast<const float4*>(&sA[buf][kk][ty*8+4]);
            float4 bv  = *reinterpret_cast<const float4*>(&sB[buf][kk][tx*4]);
            float a[8] = {av0.x, av0.y, av0.z, av0.w, av1.x, av1.y, av1.z, av1.w};
            float b[4] = {bv.x, bv.y, bv.z, bv.w};
            #pragma unroll
            for (int i = 0; i < 8; i++)
                #pragma unroll
                for (int j = 0; j < 4; j++) acc[i][j] += a[i] * b[j];
        }
        if (has_next) {
            const int nb = buf ^ 1;
            sA[nb][lc+0][lr]    = pa0.x; sA[nb][lc+1][lr]    = pa0.y;
            sA[nb][lc+2][lr]    = pa0.z; sA[nb][lc+3][lr]    = pa0.w;
            sA[nb][lc+0][64+lr] = pa1.x; sA[nb][lc+1][64+lr] = pa1.y;
            sA[nb][lc+2][64+lr] = pa1.z; sA[nb][lc+3][64+lr] = pa1.w;
            sB[nb][lc+0][lr] = pb.x; sB[nb][lc+1][lr] = pb.y;
            sB[nb][lc+2][lr] = pb.z; sB[nb][lc+3][lr] = pb.w;
            __syncthreads();
            buf = nb;
        }
    }

    #pragma unroll
    for (int i = 0; i < 8; i++) {
        const int gm = row0 + ty*8 + i;
        #pragma unroll
        for (int j = 0; j < 4; j++) {
            int gn = col0 + tx*4 + j;
            if (gn < N)
                C[(size_t)gm * ldc + gn] = acc[i][j] + (bias ? bias[gn] : 0.f);
        }
    }
}

// ---------------- small generic GEMM (decoder init only) -------------------
__global__ void gemm32t(const float* __restrict__ A, int lda,
                        const float* __restrict__ Bm, int ldb,
                        float* __restrict__ C, int ldc,
                        const float* __restrict__ bias,
                        int M, int N, int K)
{
    __shared__ float sA[32][33];
    __shared__ float sB[32][33];
    const int tid = threadIdx.x;
    const int tx = tid & 15, ty = tid >> 4;
    const int row0 = blockIdx.y * 32, col0 = blockIdx.x * 32;

    float acc[2][2] = {{0,0},{0,0}};
    for (int k0 = 0; k0 < K; k0 += 32) {
        #pragma unroll
        for (int i = tid; i < 1024; i += 256) {
            int m = i >> 5, kk = i & 31;
            sA[kk][m] = A[(size_t)(row0 + m) * lda + k0 + kk];
            sB[kk][m] = Bm[(size_t)(col0 + m) * ldb + k0 + kk];
        }
        __syncthreads();
        #pragma unroll
        for (int kk = 0; kk < 32; kk++) {
            float a0 = sA[kk][ty*2], a1 = sA[kk][ty*2+1];
            float b0 = sB[kk][tx*2], b1 = sB[kk][tx*2+1];
            acc[0][0] += a0*b0; acc[0][1] += a0*b1;
            acc[1][0] += a1*b0; acc[1][1] += a1*b1;
        }
        __syncthreads();
    }
    #pragma unroll
    for (int i = 0; i < 2; i++)
        #pragma unroll
        for (int j = 0; j < 2; j++) {
            int gm = row0 + ty*2 + i, gn = col0 + tx*2 + j;
            C[(size_t)gm * ldc + gn] = tanhf(acc[i][j] + bias[gn]);
        }
}

// =====================================================================
//  Encoder fused step
// =====================================================================
__global__ __launch_bounds__(256)
void enc_step_kernel(const float* __restrict__ hf_in,  const float* __restrict__ hb_in,
                     float* __restrict__ hf_out, float* __restrict__ hb_out,
                     const float* __restrict__ Whh_f, const float* __restrict__ Whh_b,
                     const float* __restrict__ bhh_f, const float* __restrict__ bhh_b,
                     const float* __restrict__ xpf,   const float* __restrict__ xpb,
                     float* __restrict__ enc_out, int t)
{
    const int dir = blockIdx.z;
    const float* hin  = dir ? hb_in  : hf_in;
    const float* Whh  = dir ? Whh_b  : Whh_f;
    const float* bhh  = dir ? bhh_b  : bhh_f;
    const float* xp   = dir ? xpb    : xpf;
    float*       hout = dir ? hb_out : hf_out;
    const int s = dir ? (Ss - 1 - t) : t;

    const int j0 = blockIdx.x * 32, b0 = blockIdx.y * 32;
    const int tid = threadIdx.x;
    const int tx = tid & 15, ty = tid >> 4;

    __shared__ float sH[16][33];
    __shared__ float sW[3][16][34];

    float acc[2][2][3];
    #pragma unroll
    for (int bi = 0; bi < 2; bi++)
        #pragma unroll
        for (int ji = 0; ji < 2; ji++)
            #pragma unroll
            for (int g = 0; g < 3; g++) acc[bi][ji][g] = 0.f;

    for (int k0 = 0; k0 < Hh; k0 += 16) {
        #pragma unroll
        for (int i = tid; i < 512; i += 256) {
            int b = i >> 4, kk = i & 15;
            sH[kk][b] = hin[(size_t)(b0 + b) * Hh + k0 + kk];
        }
        #pragma unroll
        for (int i = tid; i < 1536; i += 256) {
            int r = i >> 4, kk = i & 15;
            int g = r / 32, j = r % 32;
            sW[g][kk][j] = Whh[(size_t)(g * Hh + j0 + j) * Hh + k0 + kk];
        }
        __syncthreads();
        #pragma unroll
        for (int kk = 0; kk < 16; kk++) {
            float hv[2] = { sH[kk][ty*2], sH[kk][ty*2 + 1] };
            #pragma unroll
            for (int g = 0; g < 3; g++) {
                float w0 = sW[g][kk][tx*2], w1 = sW[g][kk][tx*2 + 1];
                acc[0][0][g] += hv[0] * w0;
                acc[0][1][g] += hv[0] * w1;
                acc[1][0][g] += hv[1] * w0;
                acc[1][1][g] += hv[1] * w1;
            }
        }
        __syncthreads();
    }

    #pragma unroll
    for (int bi = 0; bi < 2; bi++) {
        int b = b0 + ty*2 + bi;
        #pragma unroll
        for (int ji = 0; ji < 2; ji++) {
            int j = j0 + tx*2 + ji;
            float rh = acc[bi][ji][0] + bhh[j];
            float zh = acc[bi][ji][1] + bhh[Hh + j];
            float nh = acc[bi][ji][2] + bhh[2*Hh + j];
            const float* x = xp + ((size_t)b * Ss + s) * (3*Hh);
            float r = sigf(x[j] + rh);
            float z = sigf(x[Hh + j] + zh);
            float n = tanhf(x[2*Hh + j] + r * nh);
            float hv = hin[(size_t)b * Hh + j];
            float hn = (1.f - z) * n + z * hv;
            hout[(size_t)b * Hh + j] = hn;
            enc_out[((size_t)b * Ss + s) * (2*Hh) + dir * Hh + j] = hn;
        }
    }
}

// =====================================================================
//  Decoder fused GRU step (writes hid + tf32-split catHL)
// =====================================================================
__global__ __launch_bounds__(256)
void dec_fused_kernel(const float* __restrict__ rnin,
                      const float* __restrict__ hid_in,
                      const float* __restrict__ dec_Wih,
                      const float* __restrict__ dec_Whh,
                      const float* __restrict__ dec_bih,
                      const float* __restrict__ dec_bhh,
                      float* __restrict__ hid_out, float2* __restrict__ catHL,
                      unsigned long long* __restrict__ slots)
{
    const int j0 = blockIdx.x * 32, b0 = blockIdx.y * 32;
    const int tid = threadIdx.x;
    const int tx = tid & 15, ty = tid >> 4;

    __shared__ float sH[16][33];
    __shared__ float sW[4][16][34];

    float acc[2][2][4];
    #pragma unroll
    for (int bi = 0; bi < 2; bi++)
        #pragma unroll
        for (int ji = 0; ji < 2; ji++)
            #pragma unroll
            for (int g = 0; g < 4; g++) acc[bi][ji][g] = 0.f;

    for (int k0 = 0; k0 < RNK + Dd; k0 += 16) {
        const bool ih = (k0 < RNK);
        #pragma unroll
        for (int i = tid; i < 512; i += 256) {
            int b = i >> 4, kk = i & 15;
            sH[kk][b] = ih ? rnin[(size_t)(b0 + b) * RNK + k0 + kk]
                           : hid_in[(size_t)(b0 + b) * Dd + (k0 - RNK) + kk];
        }
        #pragma unroll
        for (int i = tid; i < 2048; i += 256) {
            int g = i >> 9;
            int r = (i >> 4) & 31;
            int kk = i & 15;
            int j = j0 + r;
            float w;
            if (ih) {
                w = (g == 3) ? 0.f
                    : dec_Wih[(size_t)(g * Dd + j) * RNK + k0 + kk];
            } else {
                w = (g == 2) ? 0.f
                    : dec_Whh[(size_t)(((g == 3) ? 2 : g) * Dd + j) * Dd + (k0 - RNK) + kk];
            }
            sW[g][kk][r] = w;
        }
        __syncthreads();
        #pragma unroll
        for (int kk = 0; kk < 16; kk++) {
            float hv0 = sH[kk][ty*2], hv1 = sH[kk][ty*2 + 1];
            #pragma unroll
            for (int g = 0; g < 4; g++) {
                float w0 = sW[g][kk][tx*2], w1 = sW[g][kk][tx*2 + 1];
                acc[0][0][g] += hv0 * w0;
                acc[0][1][g] += hv0 * w1;
                acc[1][0][g] += hv1 * w0;
                acc[1][1][g] += hv1 * w1;
            }
        }
        __syncthreads();
    }

    #pragma unroll
    for (int bi = 0; bi < 2; bi++) {
        int b = b0 + ty*2 + bi;
        #pragma unroll
        for (int ji = 0; ji < 2; ji++) {
            int j = j0 + tx*2 + ji;
            float r = sigf(acc[bi][ji][0] + dec_bih[j] + dec_bhh[j]);
            float z = sigf(acc[bi][ji][1] + dec_bih[Dd + j] + dec_bhh[Dd + j]);
            float n = tanhf(acc[bi][ji][2] + dec_bih[2*Dd + j]
                            + r * (acc[bi][ji][3] + dec_bhh[2*Dd + j]));
            float hv = hid_in[(size_t)b * Dd + j];
            float hn = (1.f - z) * n + z * hv;
            hid_out[(size_t)b * Dd + j] = hn;
            catHL[(size_t)b * CAT + j] = tf32_split2(hn);
            if (j == 0) slots[b] = 0ull;
        }
    }
}

// ---------------- small helper kernels ------------------------------------
__global__ void init0_kernel(float* hf, float* hb, unsigned long long* slots)
{
    int i = blockIdx.x * 256 + threadIdx.x;
    if (i < Bb * Hh) { hf[i] = 0.f; hb[i] = 0.f; }
    if (i < Bb)
        slots[i] = ((unsigned long long)fmono(0.f) << 32) | 0xFFFFFFFFull;
}

__global__ void embed_kernel(const int* __restrict__ inp,
                             const float* __restrict__ tab,
                             float* __restrict__ emb)
{
    int bs = blockIdx.x, j = threadIdx.x;
    int tk = inp[bs * 2 + 0];
    float m = (float)inp[bs * 2 + 1];
    emb[(size_t)bs * Ee + j] = tab[(size_t)tk * Ee + j] * m;
}

__global__ void transpose_attw_kernel(const float* __restrict__ attn_W,
                                      float* __restrict__ attWT)
{
    int k = blockIdx.x, j = threadIdx.x;
    attWT[(size_t)k * Aa + j] = attn_W[(size_t)j * (Dd + 2*Hh) + k];
}

__global__ void concat_fc_kernel(const float* __restrict__ hf,
                                 const float* __restrict__ hb,
                                 float* __restrict__ fcin)
{
    int b = blockIdx.x, j = threadIdx.x;
    fcin[(size_t)b*2*Hh + j]      = hf[(size_t)b*Hh + j];
    fcin[(size_t)b*2*Hh + Hh + j] = hb[(size_t)b*Hh + j];
}

// attention (with fused hproj) + decoder-token embedding; writes rnin + catHL
__global__ __launch_bounds__(256)
void attn_embed_kernel(const float* __restrict__ encp,
                       const float* __restrict__ hid,
                       const float* __restrict__ attWT,
                       const float* __restrict__ enc_out,
                       const unsigned long long* __restrict__ slots,
                       const float* __restrict__ tab,
                       float* __restrict__ rnin, float2* __restrict__ catHL)
{
    int b = blockIdx.x, tid = threadIdx.x;
    int lane = tid & 31, w = tid >> 5;
    __shared__ float shid[Dd];
    __shared__ float shp[Aa];
    __shared__ float salpha[Ss];

    shid[tid] = hid[(size_t)b*Dd + tid];
    __syncthreads();

    float hp = 0.f;
    #pragma unroll 8
    for (int k = 0; k < Dd; k++) hp += shid[k] * attWT[(size_t)k * Aa + tid];
    shp[tid] = hp;
    __syncthreads();

    #pragma unroll
    for (int i = 0; i < 8; i++) {
        int s = w + 8 * i;
        const float* row = encp + ((size_t)b*Ss + s)*Aa;
        float acc = 0.f;
        #pragma unroll
        for (int a = lane; a < Aa; a += 32) acc += tanhf(row[a] + shp[a]);
        #pragma unroll
        for (int o = 16; o; o >>= 1) acc += __shfl_xor_sync(0xffffffffu, acc, o);
        if (lane == 0) salpha[s] = acc;
    }
    __syncthreads();
    if (w == 0) {
        float v0 = salpha[lane], v1 = salpha[lane + 32];
        float m = fmaxf(v0, v1);
        #pragma unroll
        for (int o = 16; o; o >>= 1) m = fmaxf(m, __shfl_xor_sync(0xffffffffu, m, o));
        float e0 = expf(v0 - m), e1 = expf(v1 - m);
        float sum = e0 + e1;
        #pragma unroll
        for (int o = 16; o; o >>= 1) sum += __shfl_xor_sync(0xffffffffu, sum, o);
        float inv = 1.f / sum;
        salpha[lane] = e0 * inv; salpha[lane + 32] = e1 * inv;
    }
    __syncthreads();
    float a0 = 0.f, a1 = 0.f;
    for (int s = 0; s < Ss; s++) {
        float al = salpha[s];
        const float* eo = enc_out + ((size_t)b*Ss + s)*(2*Hh);
        a0 += al * eo[tid];
        a1 += al * eo[Hh + tid];
    }
    rnin[(size_t)b*RNK + Ee + tid]      = a0;
    rnin[(size_t)b*RNK + Ee + Hh + tid] = a1;
    catHL[(size_t)b*CAT + Dd + tid]      = tf32_split2(a0);
    catHL[(size_t)b*CAT + Dd + Hh + tid] = tf32_split2(a1);

    int tk = (int)(0xFFFFFFFFu - (unsigned)(slots[b] & 0xFFFFFFFFull));
    float e = tab[(size_t)tk * Ee + tid];
    rnin[(size_t)b*RNK + tid] = e;
    catHL[(size_t)b*CAT + Dd + 2*Hh + tid] = tf32_split2(e);
}

__global__ void logsoftmax_kernel(float* __restrict__ out)
{
    int row = blockIdx.x, tid = threadIdx.x;
    int s = row & (Ss - 1);
    float* p = out + (size_t)row * Vv;
    if (s == 0) {
        float L = logf(expf(1.f) + (float)(Vv - 1));
        for (int v = tid; v < Vv; v += 256) p[v] = (v == 0 ? 1.f : 0.f) - L;
        return;
    }
    constexpr int PT = (Vv + 255) / 256;
    float regs[PT];
    float m = -INFINITY;
    #pragma unroll
    for (int i = 0; i < PT; i++) {
        int v = tid + i * 256;
        if (v < Vv) { regs[i] = p[v]; m = fmaxf(m, regs[i]); }
        else regs[i] = -INFINITY;
    }
    __shared__ float sm[256];
    sm[tid] = m; __syncthreads();
    for (int o = 128; o; o >>= 1) { if (tid < o) sm[tid] = fmaxf(sm[tid], sm[tid+o]); __syncthreads(); }
    m = sm[0]; __syncthreads();
    float sum = 0.f;
    #pragma unroll
    for (int i = 0; i < PT; i++) {
        int v = tid + i * 256;
        if (v < Vv) sum += expf(regs[i] - m);
    }
    sm[tid] = sum; __syncthreads();
    for (int o = 128; o; o >>= 1) { if (tid < o) sm[tid] += sm[tid+o]; __syncthreads(); }
    float ls = m + logf(sm[0]);
    #pragma unroll
    for (int i = 0; i < PT; i++) {
        int v = tid + i * 256;
        if (v < Vv) p[v] = regs[i] - ls;
    }
}

// ---------------- launch helpers ------------------------------------------
static inline dim3 gridL(int M, int N) { return dim3((N + 63) / 64, M / 128); }

extern "C" void kernel_launch(void* const* d_in, const int* in_sizes, int n_in,
                              void* d_out, int out_size)
{
    const int*   inp       = (const int*)  d_in[0];
    const float* emb_table = (const float*)d_in[1];
    const float* Wih_f     = (const float*)d_in[2];
    const float* Whh_f     = (const float*)d_in[3];
    const float* bih_f     = (const float*)d_in[4];
    const float* bhh_f     = (const float*)d_in[5];
    const float* Wih_b     = (const float*)d_in[6];
    const float* Whh_b     = (const float*)d_in[7];
    const float* bih_b     = (const float*)d_in[8];
    const float* bhh_b     = (const float*)d_in[9];
    const float* fc_W      = (const float*)d_in[10];
    const float* fc_b      = (const float*)d_in[11];
    const float* attn_W    = (const float*)d_in[12];
    const float* attn_b    = (const float*)d_in[13];
    const float* dec_Wih   = (const float*)d_in[14];
    const float* dec_Whh   = (const float*)d_in[15];
    const float* dec_bih   = (const float*)d_in[16];
    const float* dec_bhh   = (const float*)d_in[17];
    const float* out_W     = (const float*)d_in[18];
    const float* out_b     = (const float*)d_in[19];
    float* out = (float*)d_out;

    float* scr = nullptr;
    cudaGetSymbolAddress((void**)&scr, g_scratch);
    float* emb   = scr + OFF_EMB;
    float* xpf   = scr + OFF_XPF;
    float* xpb   = scr + OFF_XPB;
    float* enco  = scr + OFF_ENCO;
    float* encp  = scr + OFF_ENCP;
    float* hf0   = scr + OFF_HF0;
    float* hf1   = scr + OFF_HF1;
    float* hb0   = scr + OFF_HB0;
    float* hb1   = scr + OFF_HB1;
    float* hid0  = scr + OFF_HID0;
    float* hid1  = scr + OFF_HID1;
    float* fcin  = scr + OFF_FCIN;
    float* rnin  = scr + OFF_RNIN;
    float* attWT = scr + OFF_ATTWT;
    float2* catHL = (float2*)(scr + OFF_CATHL);
    float2* WHL   = (float2*)(scr + OFF_WHL);
    unsigned long long* slots = (unsigned long long*)(scr + OFF_SLOT);

    // ---- init + embedding + one-time GEMMs + weight split ----
    init0_kernel<<<(Bb*Hh + 255)/256, 256>>>(hf0, hb0, slots);
    embed_kernel<<<Bb*Ss, 256>>>(inp, emb_table, emb);
    transpose_attw_kernel<<<Dd, Aa>>>(attn_W, attWT);
    split_w_kernel<<<(Vv*CAT + 255)/256, 256>>>(out_W, WHL, Vv*CAT);
    gemmL<<<gridL(Bb*Ss, 3*Hh), 256>>>(emb, Ee, Wih_f, Ee, xpf, 3*Hh, bih_f, Bb*Ss, 3*Hh, Ee);
    gemmL<<<gridL(Bb*Ss, 3*Hh), 256>>>(emb, Ee, Wih_b, Ee, xpb, 3*Hh, bih_b, Bb*Ss, 3*Hh, Ee);

    // ---- encoder recurrence ----
    for (int t = 0; t < Ss; t++) {
        const float* hfi = (t & 1) ? hf1 : hf0;
        const float* hbi = (t & 1) ? hb1 : hb0;
        float* hfo = (t & 1) ? hf0 : hf1;
        float* hbo = (t & 1) ? hb0 : hb1;
        enc_step_kernel<<<dim3(8, 4, 2), 256>>>(hfi, hbi, hfo, hbo,
                                                Whh_f, Whh_b, bhh_f, bhh_b,
                                                xpf, xpb, enco, t);
    }

    // ---- decoder init ----
    concat_fc_kernel<<<Bb, 256>>>(hf0, hb0, fcin);
    gemm32t<<<dim3(Dd/32, Bb/32), 256>>>(fcin, 2*Hh, fc_W, 2*Hh, hid0, Dd, fc_b, Bb, Dd, 2*Hh);

    // ---- attention projection of enc_out (one-time) ----
    gemmL<<<gridL(Bb*Ss, Aa), 256>>>(enco, 2*Hh, attn_W + Dd, Dd + 2*Hh, encp, Aa, attn_b, Bb*Ss, Aa, 2*Hh);

    // ---- decoder steps (3 launches each) ----
    const dim3 gTC((Vv + 63) / 64, Bb / 64);
    for (int t = 0; t < Ss - 1; t++) {
        const float* hin = (t & 1) ? hid1 : hid0;
        float*       hout = (t & 1) ? hid0 : hid1;
        attn_embed_kernel<<<Bb, 256>>>(encp, hin, attWT, enco, slots, emb_table, rnin, catHL);
        dec_fused_kernel<<<dim3(8, 4), 256>>>(rnin, hin, dec_Wih, dec_Whh,
                                              dec_bih, dec_bhh, hout, catHL, slots);
        gemmTC2<<<gTC, 256>>>(catHL, WHL, out_b,
                              out + (size_t)(t + 1) * Vv, Ss * Vv, slots);
    }

    // ---- final log-softmax ----
    logsoftmax_kernel<<<Bb*Ss, 256>>>(out);
}

// round 10
// speedup vs baseline: 1.1788x; 1.0087x over previous
#include <cuda_runtime.h>
#include <math.h>
#include <stdint.h>

// Problem dims
constexpr int Bb = 128, Ss = 64, Ee = 256, Hh = 256, Dd = 256, Aa = 256, Vv = 10000;
constexpr int CAT = Dd + 2*Hh + Ee;   // 1024
constexpr int RNK = Ee + 2*Hh;        // 768

// ---------------- scratch ---------------------------------------------------
constexpr size_t OFF_EMB   = 0;
constexpr size_t OFF_XPF   = OFF_EMB   + (size_t)Bb*Ss*Ee;
constexpr size_t OFF_XPB   = OFF_XPF   + (size_t)Bb*Ss*3*Hh;
constexpr size_t OFF_ENCO  = OFF_XPB   + (size_t)Bb*Ss*3*Hh;
constexpr size_t OFF_ENCP  = OFF_ENCO  + (size_t)Bb*Ss*2*Hh;
constexpr size_t OFF_HF0   = OFF_ENCP  + (size_t)Bb*Ss*Aa;
constexpr size_t OFF_HF1   = OFF_HF0   + (size_t)Bb*Hh;
constexpr size_t OFF_HB0   = OFF_HF1   + (size_t)Bb*Hh;
constexpr size_t OFF_HB1   = OFF_HB0   + (size_t)Bb*Hh;
constexpr size_t OFF_HID0  = OFF_HB1   + (size_t)Bb*Hh;
constexpr size_t OFF_HID1  = OFF_HID0  + (size_t)Bb*Dd;
constexpr size_t OFF_FCIN  = OFF_HID1  + (size_t)Bb*Dd;
constexpr size_t OFF_RNIN  = OFF_FCIN  + (size_t)Bb*2*Hh;
constexpr size_t OFF_ATTWT = OFF_RNIN  + (size_t)Bb*RNK;
constexpr size_t OFF_SLOT  = OFF_ATTWT + (size_t)Dd*Aa;
constexpr size_t OFF_CATHL = OFF_SLOT  + (size_t)2*Bb;           // float2 [Bb][CAT]
constexpr size_t OFF_WHL   = OFF_CATHL + (size_t)2*Bb*CAT;       // float2 [Vv][CAT]
constexpr size_t SCR_TOTAL = OFF_WHL   + (size_t)2*Vv*CAT;

__device__ __align__(256) float g_scratch[SCR_TOTAL];

__device__ __forceinline__ float sigf(float x) { return 1.f / (1.f + expf(-x)); }

__device__ __forceinline__ unsigned int fmono(float x) {
    unsigned int b = __float_as_uint(x);
    return (b & 0x80000000u) ? ~b : (b | 0x80000000u);
}

__device__ __forceinline__ float2 tf32_split2(float w) {
    unsigned int hb, lb;
    asm("cvt.rna.tf32.f32 %0, %1;" : "=r"(hb) : "f"(w));
    float hi = __uint_as_float(hb);
    float res = w - hi;
    asm("cvt.rna.tf32.f32 %0, %1;" : "=r"(lb) : "f"(res));
    return make_float2(hi, __uint_as_float(lb));
}

#define MMA_TF32(d, A0, A1, A2, A3, B0, B1)                                      \
    asm volatile("mma.sync.aligned.m16n8k8.row.col.f32.tf32.tf32.f32 "           \
                 "{%0,%1,%2,%3}, {%4,%5,%6,%7}, {%8,%9}, {%0,%1,%2,%3};"          \
                 : "+f"(d[0]), "+f"(d[1]), "+f"(d[2]), "+f"(d[3])                 \
                 : "r"(__float_as_uint(A0)), "r"(__float_as_uint(A1)),            \
                   "r"(__float_as_uint(A2)), "r"(__float_as_uint(A3)),            \
                   "r"(__float_as_uint(B0)), "r"(__float_as_uint(B1)))

// =====================================================================
//  one-time: split out_W into interleaved (hi,lo) float2 plane
// =====================================================================
__global__ void split_w_kernel(const float* __restrict__ W,
                               float2* __restrict__ WHL, int total)
{
    int i = blockIdx.x * 256 + threadIdx.x;
    if (i < total) WHL[i] = tf32_split2(W[i]);
}

// =====================================================================
//  gemmTC2: logits GEMM via tf32 mma.sync, 3-term split, pre-split inputs.
//  C[128, Vv] = cat[128,1024] @ W[Vv,1024]^T + bias, fused argmax.
//  grid (157, 2), 256 threads (8 warps = 4 m-tiles x 2 n-halves).
//  BM=64, BN=64, BK=16, double-buffered, float4 global loads.
//  Round-10 change: term-outer / nt-inner MMA order — breaks the 3-deep
//  same-accumulator RAW chain that serialized round 8.
// =====================================================================
__global__ __launch_bounds__(256)
void gemmTC2(const float2* __restrict__ AHL,
             const float2* __restrict__ WHL,
             const float* __restrict__ bias,
             float* __restrict__ C, int ldc,
             unsigned long long* __restrict__ slots)
{
    constexpr int K = CAT;
    constexpr int N = Vv;
    constexpr int NCH = K / 16;          // 64 chunks
    __shared__ __align__(16) float2 sA[2][64][20];
    __shared__ __align__(16) float2 sB[2][64][20];

    const int tid  = threadIdx.x;
    const int lane = tid & 31;
    const int warp = tid >> 5;
    const int wm = warp & 3;             // m tile (16 rows)
    const int wn = warp >> 2;            // n half (32 cols)
    const int g = lane >> 2;             // 0..7
    const int t = lane & 3;              // 0..3
    const int row0 = blockIdx.y * 64;
    const int col0 = blockIdx.x * 64;

    // cooperative load: each thread loads 2 float4 (=4 float2) per tensor/chunk
    const int lr  = tid >> 2;            // 0..63
    const int lc2 = (tid & 3) * 4;       // float2 col base: 0,4,8,12

    const float4* Ap = reinterpret_cast<const float4*>(AHL + (size_t)(row0 + lr) * K + lc2);
    const int gn = col0 + lr;
    const bool bv = (gn < N);
    const float4* Bp = reinterpret_cast<const float4*>(WHL + (size_t)(bv ? gn : 0) * K + lc2);
    const float4 z4 = make_float4(0.f, 0.f, 0.f, 0.f);

    // preload chunk 0
    float4 a0r = Ap[0], a1r = Ap[1];
    float4 b0r = bv ? Bp[0] : z4, b1r = bv ? Bp[1] : z4;
    *reinterpret_cast<float4*>(&sA[0][lr][lc2])     = a0r;
    *reinterpret_cast<float4*>(&sA[0][lr][lc2 + 2]) = a1r;
    *reinterpret_cast<float4*>(&sB[0][lr][lc2])     = b0r;
    *reinterpret_cast<float4*>(&sB[0][lr][lc2 + 2]) = b1r;
    __syncthreads();

    float acc[4][4];
    #pragma unroll
    for (int nt = 0; nt < 4; nt++)
        #pragma unroll
        for (int q = 0; q < 4; q++) acc[nt][q] = 0.f;

    int buf = 0;
    for (int ci = 0; ci < NCH; ci++) {
        const bool has_next = (ci + 1 < NCH);
        if (has_next) {
            const int f4 = (ci + 1) * 8;
            a0r = Ap[f4]; a1r = Ap[f4 + 1];
            b0r = bv ? Bp[f4] : z4; b1r = bv ? Bp[f4 + 1] : z4;
        }
        #pragma unroll
        for (int ks = 0; ks < 16; ks += 8) {
            // preload ALL fragments for this ks into registers
            float2 A0 = sA[buf][wm*16 + g][ks + t];
            float2 A1 = sA[buf][wm*16 + g + 8][ks + t];
            float2 A2 = sA[buf][wm*16 + g][ks + t + 4];
            float2 A3 = sA[buf][wm*16 + g + 8][ks + t + 4];
            float2 B0[4], B1[4];
            #pragma unroll
            for (int nt = 0; nt < 4; nt++) {
                B0[nt] = sB[buf][wn*32 + nt*8 + g][ks + t];
                B1[nt] = sB[buf][wn*32 + nt*8 + g][ks + t + 4];
            }
            // term-outer / nt-inner: 4 independent MMAs between dependent ones
            #pragma unroll
            for (int nt = 0; nt < 4; nt++)   // hi*hi
                MMA_TF32(acc[nt], A0.x, A1.x, A2.x, A3.x, B0[nt].x, B1[nt].x);
            #pragma unroll
            for (int nt = 0; nt < 4; nt++)   // hi*lo
                MMA_TF32(acc[nt], A0.x, A1.x, A2.x, A3.x, B0[nt].y, B1[nt].y);
            #pragma unroll
            for (int nt = 0; nt < 4; nt++)   // lo*hi
                MMA_TF32(acc[nt], A0.y, A1.y, A2.y, A3.y, B0[nt].x, B1[nt].x);
        }
        if (has_next) {
            const int nb = buf ^ 1;
            *reinterpret_cast<float4*>(&sA[nb][lr][lc2])     = a0r;
            *reinterpret_cast<float4*>(&sA[nb][lr][lc2 + 2]) = a1r;
            *reinterpret_cast<float4*>(&sB[nb][lr][lc2])     = b0r;
            *reinterpret_cast<float4*>(&sB[nb][lr][lc2 + 2]) = b1r;
            __syncthreads();
            buf = nb;
        }
    }

    // ---- epilogue: bias, store, fused argmax ----
    const int gm0 = row0 + wm*16 + g;
    const int gm1 = gm0 + 8;
    float best0 = -INFINITY, best1 = -INFINITY;
    int bi0 = 0, bi1 = 0;
    #pragma unroll
    for (int nt = 0; nt < 4; nt++) {
        const int cb = col0 + wn*32 + nt*8;
        if (cb < N) {                    // N%8==0 -> tile fully valid or not
            const int c0 = cb + 2*t;
            float bv0 = bias[c0], bv1 = bias[c0 + 1];
            float v00 = acc[nt][0] + bv0;
            float v01 = acc[nt][1] + bv1;
            float v10 = acc[nt][2] + bv0;
            float v11 = acc[nt][3] + bv1;
            *reinterpret_cast<float2*>(&C[(size_t)gm0 * ldc + c0]) = make_float2(v00, v01);
            *reinterpret_cast<float2*>(&C[(size_t)gm1 * ldc + c0]) = make_float2(v10, v11);
            if (v00 > best0) { best0 = v00; bi0 = c0; }
            if (v01 > best0) { best0 = v01; bi0 = c0 + 1; }
            if (v10 > best1) { best1 = v10; bi1 = c0; }
            if (v11 > best1) { best1 = v11; bi1 = c0 + 1; }
        }
    }
    unsigned long long k0p =
        ((unsigned long long)fmono(best0) << 32) |
        (unsigned long long)(0xFFFFFFFFu - (unsigned)bi0);
    unsigned long long k1p =
        ((unsigned long long)fmono(best1) << 32) |
        (unsigned long long)(0xFFFFFFFFu - (unsigned)bi1);
    #pragma unroll
    for (int o = 1; o <= 2; o <<= 1) {
        unsigned long long o0 = __shfl_xor_sync(0xffffffffu, k0p, o);
        unsigned long long o1 = __shfl_xor_sync(0xffffffffu, k1p, o);
        if (o0 > k0p) k0p = o0;
        if (o1 > k1p) k1p = o1;
    }
    if (t == 0) {
        atomicMax(&slots[gm0], k0p);
        atomicMax(&slots[gm1], k1p);
    }
}

// =====================================================================
//  gemmL: big one-time GEMMs (unchanged, passing).
// =====================================================================
__global__ __launch_bounds__(256)
void gemmL(const float* __restrict__ A, int lda,
           const float* __restrict__ Bm, int ldb,
           float* __restrict__ C, int ldc,
           const float* __restrict__ bias,
           int M, int N, int K)
{
    __shared__ __align__(16) float sA[2][16][132];
    __shared__ __align__(16) float sB[2][16][68];
    const int tid = threadIdx.x;
    const int tx = tid & 15, ty = tid >> 4;
    const int row0 = blockIdx.y * 128, col0 = blockIdx.x * 64;
    const int lr = tid >> 2;
    const int lc = (tid & 3) * 4;

    const float* Aptr0 = A + (size_t)(row0 + lr) * lda + lc;
    const float* Aptr1 = A + (size_t)(row0 + 64 + lr) * lda + lc;
    const int gnl = col0 + lr;
    const int gnc = (gnl < N) ? gnl : (N - 1);
    const float* Bptr = Bm + (size_t)gnc * ldb + lc;
    const bool bval = (gnl < N);

    float4 pa0 = *reinterpret_cast<const float4*>(Aptr0);
    float4 pa1 = *reinterpret_cast<const float4*>(Aptr1);
    float4 pb  = *reinterpret_cast<const float4*>(Bptr);
    if (!bval) pb = make_float4(0.f, 0.f, 0.f, 0.f);

    sA[0][lc+0][lr]    = pa0.x; sA[0][lc+1][lr]    = pa0.y;
    sA[0][lc+2][lr]    = pa0.z; sA[0][lc+3][lr]    = pa0.w;
    sA[0][lc+0][64+lr] = pa1.x; sA[0][lc+1][64+lr] = pa1.y;
    sA[0][lc+2][64+lr] = pa1.z; sA[0][lc+3][64+lr] = pa1.w;
    sB[0][lc+0][lr] = pb.x; sB[0][lc+1][lr] = pb.y;
    sB[0][lc+2][lr] = pb.z; sB[0][lc+3][lr] = pb.w;
    __syncthreads();

    float acc[8][4];
    #pragma unroll
    for (int i = 0; i < 8; i++)
        #pragma unroll
        for (int j = 0; j < 4; j++) acc[i][j] = 0.f;

    int buf = 0;
    for (int k0 = 16; k0 <= K; k0 += 16) {
        const bool has_next = (k0 < K);
        if (has_next) {
            pa0 = *reinterpret_cast<const float4*>(Aptr0 + k0);
            pa1 = *reinterpret_cast<const float4*>(Aptr1 + k0);
            pb  = *reinterpret_cast<const float4*>(Bptr + k0);
            if (!bval) pb = make_float4(0.f, 0.f, 0.f, 0.f);
        }
        #pragma unroll
        for (int kk = 0; kk < 16; kk++) {
            float4 av0 = *reinterpret_cast<const float4*>(&sA[buf][kk][ty*8]);
            float4 av1 = *reinterpret_cast<const float4*>(&sA[buf][kk][ty*8+4]);
            float4 bv  = *reinterpret_cast<const float4*>(&sB[buf][kk][tx*4]);
            float a[8] = {av0.x, av0.y, av0.z, av0.w, av1.x, av1.y, av1.z, av1.w};
            float b[4] = {bv.x, bv.y, bv.z, bv.w};
            #pragma unroll
            for (int i = 0; i < 8; i++)
                #pragma unroll
                for (int j = 0; j < 4; j++) acc[i][j] += a[i] * b[j];
        }
        if (has_next) {
            const int nb = buf ^ 1;
            sA[nb][lc+0][lr]    = pa0.x; sA[nb][lc+1][lr]    = pa0.y;
            sA[nb][lc+2][lr]    = pa0.z; sA[nb][lc+3][lr]    = pa0.w;
            sA[nb][lc+0][64+lr] = pa1.x; sA[nb][lc+1][64+lr] = pa1.y;
            sA[nb][lc+2][64+lr] = pa1.z; sA[nb][lc+3][64+lr] = pa1.w;
            sB[nb][lc+0][lr] = pb.x; sB[nb][lc+1][lr] = pb.y;
            sB[nb][lc+2][lr] = pb.z; sB[nb][lc+3][lr] = pb.w;
            __syncthreads();
            buf = nb;
        }
    }

    #pragma unroll
    for (int i = 0; i < 8; i++) {
        const int gm = row0 + ty*8 + i;
        #pragma unroll
        for (int j = 0; j < 4; j++) {
            int gn = col0 + tx*4 + j;
            if (gn < N)
                C[(size_t)gm * ldc + gn] = acc[i][j] + (bias ? bias[gn] : 0.f);
        }
    }
}

// ---------------- small generic GEMM (decoder init only) -------------------
__global__ void gemm32t(const float* __restrict__ A, int lda,
                        const float* __restrict__ Bm, int ldb,
                        float* __restrict__ C, int ldc,
                        const float* __restrict__ bias,
                        int M, int N, int K)
{
    __shared__ float sA[32][33];
    __shared__ float sB[32][33];
    const int tid = threadIdx.x;
    const int tx = tid & 15, ty = tid >> 4;
    const int row0 = blockIdx.y * 32, col0 = blockIdx.x * 32;

    float acc[2][2] = {{0,0},{0,0}};
    for (int k0 = 0; k0 < K; k0 += 32) {
        #pragma unroll
        for (int i = tid; i < 1024; i += 256) {
            int m = i >> 5, kk = i & 31;
            sA[kk][m] = A[(size_t)(row0 + m) * lda + k0 + kk];
            sB[kk][m] = Bm[(size_t)(col0 + m) * ldb + k0 + kk];
        }
        __syncthreads();
        #pragma unroll
        for (int kk = 0; kk < 32; kk++) {
            float a0 = sA[kk][ty*2], a1 = sA[kk][ty*2+1];
            float b0 = sB[kk][tx*2], b1 = sB[kk][tx*2+1];
            acc[0][0] += a0*b0; acc[0][1] += a0*b1;
            acc[1][0] += a1*b0; acc[1][1] += a1*b1;
        }
        __syncthreads();
    }
    #pragma unroll
    for (int i = 0; i < 2; i++)
        #pragma unroll
        for (int j = 0; j < 2; j++) {
            int gm = row0 + ty*2 + i, gn = col0 + tx*2 + j;
            C[(size_t)gm * ldc + gn] = tanhf(acc[i][j] + bias[gn]);
        }
}

// =====================================================================
//  Encoder fused step
// =====================================================================
__global__ __launch_bounds__(256)
void enc_step_kernel(const float* __restrict__ hf_in,  const float* __restrict__ hb_in,
                     float* __restrict__ hf_out, float* __restrict__ hb_out,
                     const float* __restrict__ Whh_f, const float* __restrict__ Whh_b,
                     const float* __restrict__ bhh_f, const float* __restrict__ bhh_b,
                     const float* __restrict__ xpf,   const float* __restrict__ xpb,
                     float* __restrict__ enc_out, int t)
{
    const int dir = blockIdx.z;
    const float* hin  = dir ? hb_in  : hf_in;
    const float* Whh  = dir ? Whh_b  : Whh_f;
    const float* bhh  = dir ? bhh_b  : bhh_f;
    const float* xp   = dir ? xpb    : xpf;
    float*       hout = dir ? hb_out : hf_out;
    const int s = dir ? (Ss - 1 - t) : t;

    const int j0 = blockIdx.x * 32, b0 = blockIdx.y * 32;
    const int tid = threadIdx.x;
    const int tx = tid & 15, ty = tid >> 4;

    __shared__ float sH[16][33];
    __shared__ float sW[3][16][34];

    float acc[2][2][3];
    #pragma unroll
    for (int bi = 0; bi < 2; bi++)
        #pragma unroll
        for (int ji = 0; ji < 2; ji++)
            #pragma unroll
            for (int g = 0; g < 3; g++) acc[bi][ji][g] = 0.f;

    for (int k0 = 0; k0 < Hh; k0 += 16) {
        #pragma unroll
        for (int i = tid; i < 512; i += 256) {
            int b = i >> 4, kk = i & 15;
            sH[kk][b] = hin[(size_t)(b0 + b) * Hh + k0 + kk];
        }
        #pragma unroll
        for (int i = tid; i < 1536; i += 256) {
            int r = i >> 4, kk = i & 15;
            int g = r / 32, j = r % 32;
            sW[g][kk][j] = Whh[(size_t)(g * Hh + j0 + j) * Hh + k0 + kk];
        }
        __syncthreads();
        #pragma unroll
        for (int kk = 0; kk < 16; kk++) {
            float hv[2] = { sH[kk][ty*2], sH[kk][ty*2 + 1] };
            #pragma unroll
            for (int g = 0; g < 3; g++) {
                float w0 = sW[g][kk][tx*2], w1 = sW[g][kk][tx*2 + 1];
                acc[0][0][g] += hv[0] * w0;
                acc[0][1][g] += hv[0] * w1;
                acc[1][0][g] += hv[1] * w0;
                acc[1][1][g] += hv[1] * w1;
            }
        }
        __syncthreads();
    }

    #pragma unroll
    for (int bi = 0; bi < 2; bi++) {
        int b = b0 + ty*2 + bi;
        #pragma unroll
        for (int ji = 0; ji < 2; ji++) {
            int j = j0 + tx*2 + ji;
            float rh = acc[bi][ji][0] + bhh[j];
            float zh = acc[bi][ji][1] + bhh[Hh + j];
            float nh = acc[bi][ji][2] + bhh[2*Hh + j];
            const float* x = xp + ((size_t)b * Ss + s) * (3*Hh);
            float r = sigf(x[j] + rh);
            float z = sigf(x[Hh + j] + zh);
            float n = tanhf(x[2*Hh + j] + r * nh);
            float hv = hin[(size_t)b * Hh + j];
            float hn = (1.f - z) * n + z * hv;
            hout[(size_t)b * Hh + j] = hn;
            enc_out[((size_t)b * Ss + s) * (2*Hh) + dir * Hh + j] = hn;
        }
    }
}

// =====================================================================
//  Decoder fused GRU step (writes hid + tf32-split catHL)
// =====================================================================
__global__ __launch_bounds__(256)
void dec_fused_kernel(const float* __restrict__ rnin,
                      const float* __restrict__ hid_in,
                      const float* __restrict__ dec_Wih,
                      const float* __restrict__ dec_Whh,
                      const float* __restrict__ dec_bih,
                      const float* __restrict__ dec_bhh,
                      float* __restrict__ hid_out, float2* __restrict__ catHL,
                      unsigned long long* __restrict__ slots)
{
    const int j0 = blockIdx.x * 32, b0 = blockIdx.y * 32;
    const int tid = threadIdx.x;
    const int tx = tid & 15, ty = tid >> 4;

    __shared__ float sH[16][33];
    __shared__ float sW[4][16][34];

    float acc[2][2][4];
    #pragma unroll
    for (int bi = 0; bi < 2; bi++)
        #pragma unroll
        for (int ji = 0; ji < 2; ji++)
            #pragma unroll
            for (int g = 0; g < 4; g++) acc[bi][ji][g] = 0.f;

    for (int k0 = 0; k0 < RNK + Dd; k0 += 16) {
        const bool ih = (k0 < RNK);
        #pragma unroll
        for (int i = tid; i < 512; i += 256) {
            int b = i >> 4, kk = i & 15;
            sH[kk][b] = ih ? rnin[(size_t)(b0 + b) * RNK + k0 + kk]
                           : hid_in[(size_t)(b0 + b) * Dd + (k0 - RNK) + kk];
        }
        #pragma unroll
        for (int i = tid; i < 2048; i += 256) {
            int g = i >> 9;
            int r = (i >> 4) & 31;
            int kk = i & 15;
            int j = j0 + r;
            float w;
            if (ih) {
                w = (g == 3) ? 0.f
                    : dec_Wih[(size_t)(g * Dd + j) * RNK + k0 + kk];
            } else {
                w = (g == 2) ? 0.f
                    : dec_Whh[(size_t)(((g == 3) ? 2 : g) * Dd + j) * Dd + (k0 - RNK) + kk];
            }
            sW[g][kk][r] = w;
        }
        __syncthreads();
        #pragma unroll
        for (int kk = 0; kk < 16; kk++) {
            float hv0 = sH[kk][ty*2], hv1 = sH[kk][ty*2 + 1];
            #pragma unroll
            for (int g = 0; g < 4; g++) {
                float w0 = sW[g][kk][tx*2], w1 = sW[g][kk][tx*2 + 1];
                acc[0][0][g] += hv0 * w0;
                acc[0][1][g] += hv0 * w1;
                acc[1][0][g] += hv1 * w0;
                acc[1][1][g] += hv1 * w1;
            }
        }
        __syncthreads();
    }

    #pragma unroll
    for (int bi = 0; bi < 2; bi++) {
        int b = b0 + ty*2 + bi;
        #pragma unroll
        for (int ji = 0; ji < 2; ji++) {
            int j = j0 + tx*2 + ji;
            float r = sigf(acc[bi][ji][0] + dec_bih[j] + dec_bhh[j]);
            float z = sigf(acc[bi][ji][1] + dec_bih[Dd + j] + dec_bhh[Dd + j]);
            float n = tanhf(acc[bi][ji][2] + dec_bih[2*Dd + j]
                            + r * (acc[bi][ji][3] + dec_bhh[2*Dd + j]));
            float hv = hid_in[(size_t)b * Dd + j];
            float hn = (1.f - z) * n + z * hv;
            hid_out[(size_t)b * Dd + j] = hn;
            catHL[(size_t)b * CAT + j] = tf32_split2(hn);
            if (j == 0) slots[b] = 0ull;
        }
    }
}

// ---------------- small helper kernels ------------------------------------
__global__ void init0_kernel(float* hf, float* hb, unsigned long long* slots)
{
    int i = blockIdx.x * 256 + threadIdx.x;
    if (i < Bb * Hh) { hf[i] = 0.f; hb[i] = 0.f; }
    if (i < Bb)
        slots[i] = ((unsigned long long)fmono(0.f) << 32) | 0xFFFFFFFFull;
}

__global__ void embed_kernel(const int* __restrict__ inp,
                             const float* __restrict__ tab,
                             float* __restrict__ emb)
{
    int bs = blockIdx.x, j = threadIdx.x;
    int tk = inp[bs * 2 + 0];
    float m = (float)inp[bs * 2 + 1];
    emb[(size_t)bs * Ee + j] = tab[(size_t)tk * Ee + j] * m;
}

__global__ void transpose_attw_kernel(const float* __restrict__ attn_W,
                                      float* __restrict__ attWT)
{
    int k = blockIdx.x, j = threadIdx.x;
    attWT[(size_t)k * Aa + j] = attn_W[(size_t)j * (Dd + 2*Hh) + k];
}

__global__ void concat_fc_kernel(const float* __restrict__ hf,
                                 const float* __restrict__ hb,
                                 float* __restrict__ fcin)
{
    int b = blockIdx.x, j = threadIdx.x;
    fcin[(size_t)b*2*Hh + j]      = hf[(size_t)b*Hh + j];
    fcin[(size_t)b*2*Hh + Hh + j] = hb[(size_t)b*Hh + j];
}

// attention (with fused hproj) + decoder-token embedding; writes rnin + catHL
__global__ __launch_bounds__(256)
void attn_embed_kernel(const float* __restrict__ encp,
                       const float* __restrict__ hid,
                       const float* __restrict__ attWT,
                       const float* __restrict__ enc_out,
                       const unsigned long long* __restrict__ slots,
                       const float* __restrict__ tab,
                       float* __restrict__ rnin, float2* __restrict__ catHL)
{
    int b = blockIdx.x, tid = threadIdx.x;
    int lane = tid & 31, w = tid >> 5;
    __shared__ float shid[Dd];
    __shared__ float shp[Aa];
    __shared__ float salpha[Ss];

    shid[tid] = hid[(size_t)b*Dd + tid];
    __syncthreads();

    float hp = 0.f;
    #pragma unroll 8
    for (int k = 0; k < Dd; k++) hp += shid[k] * attWT[(size_t)k * Aa + tid];
    shp[tid] = hp;
    __syncthreads();

    #pragma unroll
    for (int i = 0; i < 8; i++) {
        int s = w + 8 * i;
        const float* row = encp + ((size_t)b*Ss + s)*Aa;
        float acc = 0.f;
        #pragma unroll
        for (int a = lane; a < Aa; a += 32) acc += tanhf(row[a] + shp[a]);
        #pragma unroll
        for (int o = 16; o; o >>= 1) acc += __shfl_xor_sync(0xffffffffu, acc, o);
        if (lane == 0) salpha[s] = acc;
    }
    __syncthreads();
    if (w == 0) {
        float v0 = salpha[lane], v1 = salpha[lane + 32];
        float m = fmaxf(v0, v1);
        #pragma unroll
        for (int o = 16; o; o >>= 1) m = fmaxf(m, __shfl_xor_sync(0xffffffffu, m, o));
        float e0 = expf(v0 - m), e1 = expf(v1 - m);
        float sum = e0 + e1;
        #pragma unroll
        for (int o = 16; o; o >>= 1) sum += __shfl_xor_sync(0xffffffffu, sum, o);
        float inv = 1.f / sum;
        salpha[lane] = e0 * inv; salpha[lane + 32] = e1 * inv;
    }
    __syncthreads();
    float a0 = 0.f, a1 = 0.f;
    for (int s = 0; s < Ss; s++) {
        float al = salpha[s];
        const float* eo = enc_out + ((size_t)b*Ss + s)*(2*Hh);
        a0 += al * eo[tid];
        a1 += al * eo[Hh + tid];
    }
    rnin[(size_t)b*RNK + Ee + tid]      = a0;
    rnin[(size_t)b*RNK + Ee + Hh + tid] = a1;
    catHL[(size_t)b*CAT + Dd + tid]      = tf32_split2(a0);
    catHL[(size_t)b*CAT + Dd + Hh + tid] = tf32_split2(a1);

    int tk = (int)(0xFFFFFFFFu - (unsigned)(slots[b] & 0xFFFFFFFFull));
    float e = tab[(size_t)tk * Ee + tid];
    rnin[(size_t)b*RNK + tid] = e;
    catHL[(size_t)b*CAT + Dd + 2*Hh + tid] = tf32_split2(e);
}

__global__ void logsoftmax_kernel(float* __restrict__ out)
{
    int row = blockIdx.x, tid = threadIdx.x;
    int s = row & (Ss - 1);
    float* p = out + (size_t)row * Vv;
    if (s == 0) {
        float L = logf(expf(1.f) + (float)(Vv - 1));
        for (int v = tid; v < Vv; v += 256) p[v] = (v == 0 ? 1.f : 0.f) - L;
        return;
    }
    constexpr int PT = (Vv + 255) / 256;
    float regs[PT];
    float m = -INFINITY;
    #pragma unroll
    for (int i = 0; i < PT; i++) {
        int v = tid + i * 256;
        if (v < Vv) { regs[i] = p[v]; m = fmaxf(m, regs[i]); }
        else regs[i] = -INFINITY;
    }
    __shared__ float sm[256];
    sm[tid] = m; __syncthreads();
    for (int o = 128; o; o >>= 1) { if (tid < o) sm[tid] = fmaxf(sm[tid], sm[tid+o]); __syncthreads(); }
    m = sm[0]; __syncthreads();
    float sum = 0.f;
    #pragma unroll
    for (int i = 0; i < PT; i++) {
        int v = tid + i * 256;
        if (v < Vv) sum += expf(regs[i] - m);
    }
    sm[tid] = sum; __syncthreads();
    for (int o = 128; o; o >>= 1) { if (tid < o) sm[tid] += sm[tid+o]; __syncthreads(); }
    float ls = m + logf(sm[0]);
    #pragma unroll
    for (int i = 0; i < PT; i++) {
        int v = tid + i * 256;
        if (v < Vv) p[v] = regs[i] - ls;
    }
}

// ---------------- launch helpers ------------------------------------------
static inline dim3 gridL(int M, int N) { return dim3((N + 63) / 64, M / 128); }

extern "C" void kernel_launch(void* const* d_in, const int* in_sizes, int n_in,
                              void* d_out, int out_size)
{
    const int*   inp       = (const int*)  d_in[0];
    const float* emb_table = (const float*)d_in[1];
    const float* Wih_f     = (const float*)d_in[2];
    const float* Whh_f     = (const float*)d_in[3];
    const float* bih_f     = (const float*)d_in[4];
    const float* bhh_f     = (const float*)d_in[5];
    const float* Wih_b     = (const float*)d_in[6];
    const float* Whh_b     = (const float*)d_in[7];
    const float* bih_b     = (const float*)d_in[8];
    const float* bhh_b     = (const float*)d_in[9];
    const float* fc_W      = (const float*)d_in[10];
    const float* fc_b      = (const float*)d_in[11];
    const float* attn_W    = (const float*)d_in[12];
    const float* attn_b    = (const float*)d_in[13];
    const float* dec_Wih   = (const float*)d_in[14];
    const float* dec_Whh   = (const float*)d_in[15];
    const float* dec_bih   = (const float*)d_in[16];
    const float* dec_bhh   = (const float*)d_in[17];
    const float* out_W     = (const float*)d_in[18];
    const float* out_b     = (const float*)d_in[19];
    float* out = (float*)d_out;

    float* scr = nullptr;
    cudaGetSymbolAddress((void**)&scr, g_scratch);
    float* emb   = scr + OFF_EMB;
    float* xpf   = scr + OFF_XPF;
    float* xpb   = scr + OFF_XPB;
    float* enco  = scr + OFF_ENCO;
    float* encp  = scr + OFF_ENCP;
    float* hf0   = scr + OFF_HF0;
    float* hf1   = scr + OFF_HF1;
    float* hb0   = scr + OFF_HB0;
    float* hb1   = scr + OFF_HB1;
    float* hid0  = scr + OFF_HID0;
    float* hid1  = scr + OFF_HID1;
    float* fcin  = scr + OFF_FCIN;
    float* rnin  = scr + OFF_RNIN;
    float* attWT = scr + OFF_ATTWT;
    float2* catHL = (float2*)(scr + OFF_CATHL);
    float2* WHL   = (float2*)(scr + OFF_WHL);
    unsigned long long* slots = (unsigned long long*)(scr + OFF_SLOT);

    // ---- init + embedding + one-time GEMMs + weight split ----
    init0_kernel<<<(Bb*Hh + 255)/256, 256>>>(hf0, hb0, slots);
    embed_kernel<<<Bb*Ss, 256>>>(inp, emb_table, emb);
    transpose_attw_kernel<<<Dd, Aa>>>(attn_W, attWT);
    split_w_kernel<<<(Vv*CAT + 255)/256, 256>>>(out_W, WHL, Vv*CAT);
    gemmL<<<gridL(Bb*Ss, 3*Hh), 256>>>(emb, Ee, Wih_f, Ee, xpf, 3*Hh, bih_f, Bb*Ss, 3*Hh, Ee);
    gemmL<<<gridL(Bb*Ss, 3*Hh), 256>>>(emb, Ee, Wih_b, Ee, xpb, 3*Hh, bih_b, Bb*Ss, 3*Hh, Ee);

    // ---- encoder recurrence ----
    for (int t = 0; t < Ss; t++) {
        const float* hfi = (t & 1) ? hf1 : hf0;
        const float* hbi = (t & 1) ? hb1 : hb0;
        float* hfo = (t & 1) ? hf0 : hf1;
        float* hbo = (t & 1) ? hb0 : hb1;
        enc_step_kernel<<<dim3(8, 4, 2), 256>>>(hfi, hbi, hfo, hbo,
                                                Whh_f, Whh_b, bhh_f, bhh_b,
                                                xpf, xpb, enco, t);
    }

    // ---- decoder init ----
    concat_fc_kernel<<<Bb, 256>>>(hf0, hb0, fcin);
    gemm32t<<<dim3(Dd/32, Bb/32), 256>>>(fcin, 2*Hh, fc_W, 2*Hh, hid0, Dd, fc_b, Bb, Dd, 2*Hh);

    // ---- attention projection of enc_out (one-time) ----
    gemmL<<<gridL(Bb*Ss, Aa), 256>>>(enco, 2*Hh, attn_W + Dd, Dd + 2*Hh, encp, Aa, attn_b, Bb*Ss, Aa, 2*Hh);

    // ---- decoder steps (3 launches each) ----
    const dim3 gTC((Vv + 63) / 64, Bb / 64);
    for (int t = 0; t < Ss - 1; t++) {
        const float* hin = (t & 1) ? hid1 : hid0;
        float*       hout = (t & 1) ? hid0 : hid1;
        attn_embed_kernel<<<Bb, 256>>>(encp, hin, attWT, enco, slots, emb_table, rnin, catHL);
        dec_fused_kernel<<<dim3(8, 4), 256>>>(rnin, hin, dec_Wih, dec_Whh,
                                              dec_bih, dec_bhh, hout, catHL, slots);
        gemmTC2<<<gTC, 256>>>(catHL, WHL, out_b,
                              out + (size_t)(t + 1) * Vv, Ss * Vv, slots);
    }

    // ---- final log-softmax ----
    logsoftmax_kernel<<<Bb*Ss, 256>>>(out);
}

// round 11
// speedup vs baseline: 1.6258x; 1.3793x over previous
#include <cuda_runtime.h>
#include <cuda_fp16.h>
#include <math.h>
#include <stdint.h>

// Problem dims
constexpr int Bb = 128, Ss = 64, Ee = 256, Hh = 256, Dd = 256, Aa = 256, Vv = 10000;
constexpr int CAT = Dd + 2*Hh + Ee;   // 1024
constexpr int RNK = Ee + 2*Hh;        // 768

// ---------------- scratch ---------------------------------------------------
constexpr size_t OFF_EMB   = 0;
constexpr size_t OFF_XPF   = OFF_EMB   + (size_t)Bb*Ss*Ee;
constexpr size_t OFF_XPB   = OFF_XPF   + (size_t)Bb*Ss*3*Hh;
constexpr size_t OFF_ENCO  = OFF_XPB   + (size_t)Bb*Ss*3*Hh;
constexpr size_t OFF_ENCP  = OFF_ENCO  + (size_t)Bb*Ss*2*Hh;
constexpr size_t OFF_HF0   = OFF_ENCP  + (size_t)Bb*Ss*Aa;
constexpr size_t OFF_HF1   = OFF_HF0   + (size_t)Bb*Hh;
constexpr size_t OFF_HB0   = OFF_HF1   + (size_t)Bb*Hh;
constexpr size_t OFF_HB1   = OFF_HB0   + (size_t)Bb*Hh;
constexpr size_t OFF_HID0  = OFF_HB1   + (size_t)Bb*Hh;
constexpr size_t OFF_HID1  = OFF_HID0  + (size_t)Bb*Dd;
constexpr size_t OFF_FCIN  = OFF_HID1  + (size_t)Bb*Dd;
constexpr size_t OFF_RNIN  = OFF_FCIN  + (size_t)Bb*2*Hh;
constexpr size_t OFF_ATTWT = OFF_RNIN  + (size_t)Bb*RNK;
constexpr size_t OFF_SLOT  = OFF_ATTWT + (size_t)Dd*Aa;
// fp16 planes (stored in float scratch; 2 halves per float)
constexpr size_t OFF_CATHI = OFF_SLOT  + (size_t)2*Bb;
constexpr size_t OFF_CATLO = OFF_CATHI + (size_t)Bb*CAT/2;
constexpr size_t OFF_WHI   = OFF_CATLO + (size_t)Bb*CAT/2;
constexpr size_t OFF_WLO   = OFF_WHI   + (size_t)Vv*CAT/2;
constexpr size_t SCR_TOTAL = OFF_WLO   + (size_t)Vv*CAT/2;

__device__ __align__(256) float g_scratch[SCR_TOTAL];

__device__ __forceinline__ float sigf(float x) { return 1.f / (1.f + expf(-x)); }

__device__ __forceinline__ unsigned int fmono(float x) {
    unsigned int b = __float_as_uint(x);
    return (b & 0x80000000u) ? ~b : (b | 0x80000000u);
}

// fp16 2-way split: x ~= hi + lo (22 mantissa bits captured)
__device__ __forceinline__ void h_split2(float x, __half& hi, __half& lo) {
    hi = __float2half_rn(x);
    lo = __float2half_rn(x - __half2float(hi));
}

#define MMA_F16(d, A0, A1, A2, A3, B0, B1)                                       \
    asm volatile("mma.sync.aligned.m16n8k16.row.col.f32.f16.f16.f32 "            \
                 "{%0,%1,%2,%3}, {%4,%5,%6,%7}, {%8,%9}, {%0,%1,%2,%3};"          \
                 : "+f"(d[0]), "+f"(d[1]), "+f"(d[2]), "+f"(d[3])                 \
                 : "r"(A0), "r"(A1), "r"(A2), "r"(A3), "r"(B0), "r"(B1))

// =====================================================================
//  one-time: split out_W into fp16 hi/lo planes
// =====================================================================
__global__ void split_w_kernel(const float* __restrict__ W,
                               __half* __restrict__ Whi,
                               __half* __restrict__ Wlo, int total)
{
    int i = blockIdx.x * 256 + threadIdx.x;
    if (i < total) {
        __half h, l;
        h_split2(W[i], h, l);
        Whi[i] = h; Wlo[i] = l;
    }
}

// =====================================================================
//  gemmH: logits GEMM via fp16 mma.sync m16n8k16, 2-way split, 3 terms.
//  C[128, Vv] = cat[128,1024] @ W[Vv,1024]^T + bias, fused argmax.
//  grid (157, 2), 256 threads (8 warps = 4 m-tiles x 2 n-halves).
//  BM=64, BN=64, chunk K=32 halves, double-buffered.
//  smem rows: 32 halves data + pad -> 20-word stride (conflict-free frags).
// =====================================================================
__global__ __launch_bounds__(256)
void gemmH(const __half* __restrict__ Ahi, const __half* __restrict__ Alo,
           const __half* __restrict__ Bhi, const __half* __restrict__ Blo,
           const float* __restrict__ bias,
           float* __restrict__ C, int ldc,
           unsigned long long* __restrict__ slots)
{
    constexpr int K = CAT;
    constexpr int N = Vv;
    constexpr int NCH = K / 32;          // 32 chunks
    // [buf][tensor A/B][plane hi/lo][row 64][word 20]  = 40960 B
    __shared__ __align__(16) uint32_t sm[2][2][2][64][20];

    const int tid  = threadIdx.x;
    const int lane = tid & 31;
    const int warp = tid >> 5;
    const int wm = warp & 3;             // m tile (16 rows)
    const int wn = warp >> 2;            // n half (32 cols)
    const int g = lane >> 2;             // 0..7
    const int t = lane & 3;              // 0..3
    const int row0 = blockIdx.y * 64;
    const int col0 = blockIdx.x * 64;

    // cooperative load: thread owns (row, q); loads 1 uint4 per (tensor,plane)
    const int lrow = (tid >> 2) & 63;    // 0..63
    const int lq   = tid & 3;            // uint4 index within chunk

    const uint4* pAh = reinterpret_cast<const uint4*>(Ahi + (size_t)(row0 + lrow) * K);
    const uint4* pAl = reinterpret_cast<const uint4*>(Alo + (size_t)(row0 + lrow) * K);
    const int gn = col0 + lrow;
    const bool bv = (gn < N);
    const uint4* pBh = reinterpret_cast<const uint4*>(Bhi + (size_t)(bv ? gn : 0) * K);
    const uint4* pBl = reinterpret_cast<const uint4*>(Blo + (size_t)(bv ? gn : 0) * K);
    const uint4 z4 = make_uint4(0u, 0u, 0u, 0u);

    // preload chunk 0
    uint4 rAh = pAh[lq], rAl = pAl[lq];
    uint4 rBh = bv ? pBh[lq] : z4, rBl = bv ? pBl[lq] : z4;
    *reinterpret_cast<uint4*>(&sm[0][0][0][lrow][lq*4]) = rAh;
    *reinterpret_cast<uint4*>(&sm[0][0][1][lrow][lq*4]) = rAl;
    *reinterpret_cast<uint4*>(&sm[0][1][0][lrow][lq*4]) = rBh;
    *reinterpret_cast<uint4*>(&sm[0][1][1][lrow][lq*4]) = rBl;
    __syncthreads();

    float acc[4][4];
    #pragma unroll
    for (int nt = 0; nt < 4; nt++)
        #pragma unroll
        for (int q = 0; q < 4; q++) acc[nt][q] = 0.f;

    int buf = 0;
    for (int ci = 0; ci < NCH; ci++) {
        const bool has_next = (ci + 1 < NCH);
        if (has_next) {
            const int i4 = (ci + 1) * 4 + lq;
            rAh = pAh[i4]; rAl = pAl[i4];
            rBh = bv ? pBh[i4] : z4; rBl = bv ? pBl[i4] : z4;
        }
        #pragma unroll
        for (int ks = 0; ks < 2; ks++) {
            const int wb = ks * 8;       // word base for this k16 slice
            const int ra0 = wm*16 + g, ra1 = ra0 + 8;
            uint32_t Ah0 = sm[buf][0][0][ra0][wb + t];
            uint32_t Ah1 = sm[buf][0][0][ra1][wb + t];
            uint32_t Ah2 = sm[buf][0][0][ra0][wb + 4 + t];
            uint32_t Ah3 = sm[buf][0][0][ra1][wb + 4 + t];
            uint32_t Al0 = sm[buf][0][1][ra0][wb + t];
            uint32_t Al1 = sm[buf][0][1][ra1][wb + t];
            uint32_t Al2 = sm[buf][0][1][ra0][wb + 4 + t];
            uint32_t Al3 = sm[buf][0][1][ra1][wb + 4 + t];
            uint32_t Bh0[4], Bh1[4], Bl0[4], Bl1[4];
            #pragma unroll
            for (int nt = 0; nt < 4; nt++) {
                const int rb = wn*32 + nt*8 + g;
                Bh0[nt] = sm[buf][1][0][rb][wb + t];
                Bh1[nt] = sm[buf][1][0][rb][wb + 4 + t];
                Bl0[nt] = sm[buf][1][1][rb][wb + t];
                Bl1[nt] = sm[buf][1][1][rb][wb + 4 + t];
            }
            #pragma unroll
            for (int nt = 0; nt < 4; nt++)   // hi*hi
                MMA_F16(acc[nt], Ah0, Ah1, Ah2, Ah3, Bh0[nt], Bh1[nt]);
            #pragma unroll
            for (int nt = 0; nt < 4; nt++)   // hi*lo
                MMA_F16(acc[nt], Ah0, Ah1, Ah2, Ah3, Bl0[nt], Bl1[nt]);
            #pragma unroll
            for (int nt = 0; nt < 4; nt++)   // lo*hi
                MMA_F16(acc[nt], Al0, Al1, Al2, Al3, Bh0[nt], Bh1[nt]);
        }
        if (has_next) {
            const int nb = buf ^ 1;
            *reinterpret_cast<uint4*>(&sm[nb][0][0][lrow][lq*4]) = rAh;
            *reinterpret_cast<uint4*>(&sm[nb][0][1][lrow][lq*4]) = rAl;
            *reinterpret_cast<uint4*>(&sm[nb][1][0][lrow][lq*4]) = rBh;
            *reinterpret_cast<uint4*>(&sm[nb][1][1][lrow][lq*4]) = rBl;
            __syncthreads();
            buf = nb;
        }
    }

    // ---- epilogue: bias, store, fused argmax (layout proven in R7/8/10) ----
    const int gm0 = row0 + wm*16 + g;
    const int gm1 = gm0 + 8;
    float best0 = -INFINITY, best1 = -INFINITY;
    int bi0 = 0, bi1 = 0;
    #pragma unroll
    for (int nt = 0; nt < 4; nt++) {
        const int cb = col0 + wn*32 + nt*8;
        if (cb < N) {                    // N%8==0 -> tile fully valid or not
            const int c0 = cb + 2*t;
            float bv0 = bias[c0], bv1 = bias[c0 + 1];
            float v00 = acc[nt][0] + bv0;
            float v01 = acc[nt][1] + bv1;
            float v10 = acc[nt][2] + bv0;
            float v11 = acc[nt][3] + bv1;
            *reinterpret_cast<float2*>(&C[(size_t)gm0 * ldc + c0]) = make_float2(v00, v01);
            *reinterpret_cast<float2*>(&C[(size_t)gm1 * ldc + c0]) = make_float2(v10, v11);
            if (v00 > best0) { best0 = v00; bi0 = c0; }
            if (v01 > best0) { best0 = v01; bi0 = c0 + 1; }
            if (v10 > best1) { best1 = v10; bi1 = c0; }
            if (v11 > best1) { best1 = v11; bi1 = c0 + 1; }
        }
    }
    unsigned long long k0p =
        ((unsigned long long)fmono(best0) << 32) |
        (unsigned long long)(0xFFFFFFFFu - (unsigned)bi0);
    unsigned long long k1p =
        ((unsigned long long)fmono(best1) << 32) |
        (unsigned long long)(0xFFFFFFFFu - (unsigned)bi1);
    #pragma unroll
    for (int o = 1; o <= 2; o <<= 1) {
        unsigned long long o0 = __shfl_xor_sync(0xffffffffu, k0p, o);
        unsigned long long o1 = __shfl_xor_sync(0xffffffffu, k1p, o);
        if (o0 > k0p) k0p = o0;
        if (o1 > k1p) k1p = o1;
    }
    if (t == 0) {
        atomicMax(&slots[gm0], k0p);
        atomicMax(&slots[gm1], k1p);
    }
}

// =====================================================================
//  gemmL: big one-time GEMMs (unchanged, passing).
// =====================================================================
__global__ __launch_bounds__(256)
void gemmL(const float* __restrict__ A, int lda,
           const float* __restrict__ Bm, int ldb,
           float* __restrict__ C, int ldc,
           const float* __restrict__ bias,
           int M, int N, int K)
{
    __shared__ __align__(16) float sA[2][16][132];
    __shared__ __align__(16) float sB[2][16][68];
    const int tid = threadIdx.x;
    const int tx = tid & 15, ty = tid >> 4;
    const int row0 = blockIdx.y * 128, col0 = blockIdx.x * 64;
    const int lr = tid >> 2;
    const int lc = (tid & 3) * 4;

    const float* Aptr0 = A + (size_t)(row0 + lr) * lda + lc;
    const float* Aptr1 = A + (size_t)(row0 + 64 + lr) * lda + lc;
    const int gnl = col0 + lr;
    const int gnc = (gnl < N) ? gnl : (N - 1);
    const float* Bptr = Bm + (size_t)gnc * ldb + lc;
    const bool bval = (gnl < N);

    float4 pa0 = *reinterpret_cast<const float4*>(Aptr0);
    float4 pa1 = *reinterpret_cast<const float4*>(Aptr1);
    float4 pb  = *reinterpret_cast<const float4*>(Bptr);
    if (!bval) pb = make_float4(0.f, 0.f, 0.f, 0.f);

    sA[0][lc+0][lr]    = pa0.x; sA[0][lc+1][lr]    = pa0.y;
    sA[0][lc+2][lr]    = pa0.z; sA[0][lc+3][lr]    = pa0.w;
    sA[0][lc+0][64+lr] = pa1.x; sA[0][lc+1][64+lr] = pa1.y;
    sA[0][lc+2][64+lr] = pa1.z; sA[0][lc+3][64+lr] = pa1.w;
    sB[0][lc+0][lr] = pb.x; sB[0][lc+1][lr] = pb.y;
    sB[0][lc+2][lr] = pb.z; sB[0][lc+3][lr] = pb.w;
    __syncthreads();

    float acc[8][4];
    #pragma unroll
    for (int i = 0; i < 8; i++)
        #pragma unroll
        for (int j = 0; j < 4; j++) acc[i][j] = 0.f;

    int buf = 0;
    for (int k0 = 16; k0 <= K; k0 += 16) {
        const bool has_next = (k0 < K);
        if (has_next) {
            pa0 = *reinterpret_cast<const float4*>(Aptr0 + k0);
            pa1 = *reinterpret_cast<const float4*>(Aptr1 + k0);
            pb  = *reinterpret_cast<const float4*>(Bptr + k0);
            if (!bval) pb = make_float4(0.f, 0.f, 0.f, 0.f);
        }
        #pragma unroll
        for (int kk = 0; kk < 16; kk++) {
            float4 av0 = *reinterpret_cast<const float4*>(&sA[buf][kk][ty*8]);
            float4 av1 = *reinterpret_cast<const float4*>(&sA[buf][kk][ty*8+4]);
            float4 bv  = *reinterpret_cast<const float4*>(&sB[buf][kk][tx*4]);
            float a[8] = {av0.x, av0.y, av0.z, av0.w, av1.x, av1.y, av1.z, av1.w};
            float b[4] = {bv.x, bv.y, bv.z, bv.w};
            #pragma unroll
            for (int i = 0; i < 8; i++)
                #pragma unroll
                for (int j = 0; j < 4; j++) acc[i][j] += a[i] * b[j];
        }
        if (has_next) {
            const int nb = buf ^ 1;
            sA[nb][lc+0][lr]    = pa0.x; sA[nb][lc+1][lr]    = pa0.y;
            sA[nb][lc+2][lr]    = pa0.z; sA[nb][lc+3][lr]    = pa0.w;
            sA[nb][lc+0][64+lr] = pa1.x; sA[nb][lc+1][64+lr] = pa1.y;
            sA[nb][lc+2][64+lr] = pa1.z; sA[nb][lc+3][64+lr] = pa1.w;
            sB[nb][lc+0][lr] = pb.x; sB[nb][lc+1][lr] = pb.y;
            sB[nb][lc+2][lr] = pb.z; sB[nb][lc+3][lr] = pb.w;
            __syncthreads();
            buf = nb;
        }
    }

    #pragma unroll
    for (int i = 0; i < 8; i++) {
        const int gm = row0 + ty*8 + i;
        #pragma unroll
        for (int j = 0; j < 4; j++) {
            int gn = col0 + tx*4 + j;
            if (gn < N)
                C[(size_t)gm * ldc + gn] = acc[i][j] + (bias ? bias[gn] : 0.f);
        }
    }
}

// ---------------- small generic GEMM (decoder init only) -------------------
__global__ void gemm32t(const float* __restrict__ A, int lda,
                        const float* __restrict__ Bm, int ldb,
                        float* __restrict__ C, int ldc,
                        const float* __restrict__ bias,
                        int M, int N, int K)
{
    __shared__ float sA[32][33];
    __shared__ float sB[32][33];
    const int tid = threadIdx.x;
    const int tx = tid & 15, ty = tid >> 4;
    const int row0 = blockIdx.y * 32, col0 = blockIdx.x * 32;

    float acc[2][2] = {{0,0},{0,0}};
    for (int k0 = 0; k0 < K; k0 += 32) {
        #pragma unroll
        for (int i = tid; i < 1024; i += 256) {
            int m = i >> 5, kk = i & 31;
            sA[kk][m] = A[(size_t)(row0 + m) * lda + k0 + kk];
            sB[kk][m] = Bm[(size_t)(col0 + m) * ldb + k0 + kk];
        }
        __syncthreads();
        #pragma unroll
        for (int kk = 0; kk < 32; kk++) {
            float a0 = sA[kk][ty*2], a1 = sA[kk][ty*2+1];
            float b0 = sB[kk][tx*2], b1 = sB[kk][tx*2+1];
            acc[0][0] += a0*b0; acc[0][1] += a0*b1;
            acc[1][0] += a1*b0; acc[1][1] += a1*b1;
        }
        __syncthreads();
    }
    #pragma unroll
    for (int i = 0; i < 2; i++)
        #pragma unroll
        for (int j = 0; j < 2; j++) {
            int gm = row0 + ty*2 + i, gn = col0 + tx*2 + j;
            C[(size_t)gm * ldc + gn] = tanhf(acc[i][j] + bias[gn]);
        }
}

// =====================================================================
//  Encoder fused step
// =====================================================================
__global__ __launch_bounds__(256)
void enc_step_kernel(const float* __restrict__ hf_in,  const float* __restrict__ hb_in,
                     float* __restrict__ hf_out, float* __restrict__ hb_out,
                     const float* __restrict__ Whh_f, const float* __restrict__ Whh_b,
                     const float* __restrict__ bhh_f, const float* __restrict__ bhh_b,
                     const float* __restrict__ xpf,   const float* __restrict__ xpb,
                     float* __restrict__ enc_out, int t)
{
    const int dir = blockIdx.z;
    const float* hin  = dir ? hb_in  : hf_in;
    const float* Whh  = dir ? Whh_b  : Whh_f;
    const float* bhh  = dir ? bhh_b  : bhh_f;
    const float* xp   = dir ? xpb    : xpf;
    float*       hout = dir ? hb_out : hf_out;
    const int s = dir ? (Ss - 1 - t) : t;

    const int j0 = blockIdx.x * 32, b0 = blockIdx.y * 32;
    const int tid = threadIdx.x;
    const int tx = tid & 15, ty = tid >> 4;

    __shared__ float sH[16][33];
    __shared__ float sW[3][16][34];

    float acc[2][2][3];
    #pragma unroll
    for (int bi = 0; bi < 2; bi++)
        #pragma unroll
        for (int ji = 0; ji < 2; ji++)
            #pragma unroll
            for (int g = 0; g < 3; g++) acc[bi][ji][g] = 0.f;

    for (int k0 = 0; k0 < Hh; k0 += 16) {
        #pragma unroll
        for (int i = tid; i < 512; i += 256) {
            int b = i >> 4, kk = i & 15;
            sH[kk][b] = hin[(size_t)(b0 + b) * Hh + k0 + kk];
        }
        #pragma unroll
        for (int i = tid; i < 1536; i += 256) {
            int r = i >> 4, kk = i & 15;
            int g = r / 32, j = r % 32;
            sW[g][kk][j] = Whh[(size_t)(g * Hh + j0 + j) * Hh + k0 + kk];
        }
        __syncthreads();
        #pragma unroll
        for (int kk = 0; kk < 16; kk++) {
            float hv[2] = { sH[kk][ty*2], sH[kk][ty*2 + 1] };
            #pragma unroll
            for (int g = 0; g < 3; g++) {
                float w0 = sW[g][kk][tx*2], w1 = sW[g][kk][tx*2 + 1];
                acc[0][0][g] += hv[0] * w0;
                acc[0][1][g] += hv[0] * w1;
                acc[1][0][g] += hv[1] * w0;
                acc[1][1][g] += hv[1] * w1;
            }
        }
        __syncthreads();
    }

    #pragma unroll
    for (int bi = 0; bi < 2; bi++) {
        int b = b0 + ty*2 + bi;
        #pragma unroll
        for (int ji = 0; ji < 2; ji++) {
            int j = j0 + tx*2 + ji;
            float rh = acc[bi][ji][0] + bhh[j];
            float zh = acc[bi][ji][1] + bhh[Hh + j];
            float nh = acc[bi][ji][2] + bhh[2*Hh + j];
            const float* x = xp + ((size_t)b * Ss + s) * (3*Hh);
            float r = sigf(x[j] + rh);
            float z = sigf(x[Hh + j] + zh);
            float n = tanhf(x[2*Hh + j] + r * nh);
            float hv = hin[(size_t)b * Hh + j];
            float hn = (1.f - z) * n + z * hv;
            hout[(size_t)b * Hh + j] = hn;
            enc_out[((size_t)b * Ss + s) * (2*Hh) + dir * Hh + j] = hn;
        }
    }
}

// =====================================================================
//  Decoder fused GRU step (writes hid + fp16 cat planes)
// =====================================================================
__global__ __launch_bounds__(256)
void dec_fused_kernel(const float* __restrict__ rnin,
                      const float* __restrict__ hid_in,
                      const float* __restrict__ dec_Wih,
                      const float* __restrict__ dec_Whh,
                      const float* __restrict__ dec_bih,
                      const float* __restrict__ dec_bhh,
                      float* __restrict__ hid_out,
                      __half* __restrict__ catHi, __half* __restrict__ catLo,
                      unsigned long long* __restrict__ slots)
{
    const int j0 = blockIdx.x * 32, b0 = blockIdx.y * 32;
    const int tid = threadIdx.x;
    const int tx = tid & 15, ty = tid >> 4;

    __shared__ float sH[16][33];
    __shared__ float sW[4][16][34];

    float acc[2][2][4];
    #pragma unroll
    for (int bi = 0; bi < 2; bi++)
        #pragma unroll
        for (int ji = 0; ji < 2; ji++)
            #pragma unroll
            for (int g = 0; g < 4; g++) acc[bi][ji][g] = 0.f;

    for (int k0 = 0; k0 < RNK + Dd; k0 += 16) {
        const bool ih = (k0 < RNK);
        #pragma unroll
        for (int i = tid; i < 512; i += 256) {
            int b = i >> 4, kk = i & 15;
            sH[kk][b] = ih ? rnin[(size_t)(b0 + b) * RNK + k0 + kk]
                           : hid_in[(size_t)(b0 + b) * Dd + (k0 - RNK) + kk];
        }
        #pragma unroll
        for (int i = tid; i < 2048; i += 256) {
            int g = i >> 9;
            int r = (i >> 4) & 31;
            int kk = i & 15;
            int j = j0 + r;
            float w;
            if (ih) {
                w = (g == 3) ? 0.f
                    : dec_Wih[(size_t)(g * Dd + j) * RNK + k0 + kk];
            } else {
                w = (g == 2) ? 0.f
                    : dec_Whh[(size_t)(((g == 3) ? 2 : g) * Dd + j) * Dd + (k0 - RNK) + kk];
            }
            sW[g][kk][r] = w;
        }
        __syncthreads();
        #pragma unroll
        for (int kk = 0; kk < 16; kk++) {
            float hv0 = sH[kk][ty*2], hv1 = sH[kk][ty*2 + 1];
            #pragma unroll
            for (int g = 0; g < 4; g++) {
                float w0 = sW[g][kk][tx*2], w1 = sW[g][kk][tx*2 + 1];
                acc[0][0][g] += hv0 * w0;
                acc[0][1][g] += hv0 * w1;
                acc[1][0][g] += hv1 * w0;
                acc[1][1][g] += hv1 * w1;
            }
        }
        __syncthreads();
    }

    #pragma unroll
    for (int bi = 0; bi < 2; bi++) {
        int b = b0 + ty*2 + bi;
        #pragma unroll
        for (int ji = 0; ji < 2; ji++) {
            int j = j0 + tx*2 + ji;
            float r = sigf(acc[bi][ji][0] + dec_bih[j] + dec_bhh[j]);
            float z = sigf(acc[bi][ji][1] + dec_bih[Dd + j] + dec_bhh[Dd + j]);
            float n = tanhf(acc[bi][ji][2] + dec_bih[2*Dd + j]
                            + r * (acc[bi][ji][3] + dec_bhh[2*Dd + j]));
            float hv = hid_in[(size_t)b * Dd + j];
            float hn = (1.f - z) * n + z * hv;
            hid_out[(size_t)b * Dd + j] = hn;
            __half h2, l2;
            h_split2(hn, h2, l2);
            catHi[(size_t)b * CAT + j] = h2;
            catLo[(size_t)b * CAT + j] = l2;
            if (j == 0) slots[b] = 0ull;
        }
    }
}

// ---------------- small helper kernels ------------------------------------
__global__ void init0_kernel(float* hf, float* hb, unsigned long long* slots)
{
    int i = blockIdx.x * 256 + threadIdx.x;
    if (i < Bb * Hh) { hf[i] = 0.f; hb[i] = 0.f; }
    if (i < Bb)
        slots[i] = ((unsigned long long)fmono(0.f) << 32) | 0xFFFFFFFFull;
}

__global__ void embed_kernel(const int* __restrict__ inp,
                             const float* __restrict__ tab,
                             float* __restrict__ emb)
{
    int bs = blockIdx.x, j = threadIdx.x;
    int tk = inp[bs * 2 + 0];
    float m = (float)inp[bs * 2 + 1];
    emb[(size_t)bs * Ee + j] = tab[(size_t)tk * Ee + j] * m;
}

__global__ void transpose_attw_kernel(const float* __restrict__ attn_W,
                                      float* __restrict__ attWT)
{
    int k = blockIdx.x, j = threadIdx.x;
    attWT[(size_t)k * Aa + j] = attn_W[(size_t)j * (Dd + 2*Hh) + k];
}

__global__ void concat_fc_kernel(const float* __restrict__ hf,
                                 const float* __restrict__ hb,
                                 float* __restrict__ fcin)
{
    int b = blockIdx.x, j = threadIdx.x;
    fcin[(size_t)b*2*Hh + j]      = hf[(size_t)b*Hh + j];
    fcin[(size_t)b*2*Hh + Hh + j] = hb[(size_t)b*Hh + j];
}

// attention (with fused hproj) + decoder-token embedding; writes rnin + cat planes
__global__ __launch_bounds__(256)
void attn_embed_kernel(const float* __restrict__ encp,
                       const float* __restrict__ hid,
                       const float* __restrict__ attWT,
                       const float* __restrict__ enc_out,
                       const unsigned long long* __restrict__ slots,
                       const float* __restrict__ tab,
                       float* __restrict__ rnin,
                       __half* __restrict__ catHi, __half* __restrict__ catLo)
{
    int b = blockIdx.x, tid = threadIdx.x;
    int lane = tid & 31, w = tid >> 5;
    __shared__ float shid[Dd];
    __shared__ float shp[Aa];
    __shared__ float salpha[Ss];

    shid[tid] = hid[(size_t)b*Dd + tid];
    __syncthreads();

    float hp = 0.f;
    #pragma unroll 8
    for (int k = 0; k < Dd; k++) hp += shid[k] * attWT[(size_t)k * Aa + tid];
    shp[tid] = hp;
    __syncthreads();

    #pragma unroll
    for (int i = 0; i < 8; i++) {
        int s = w + 8 * i;
        const float* row = encp + ((size_t)b*Ss + s)*Aa;
        float acc = 0.f;
        #pragma unroll
        for (int a = lane; a < Aa; a += 32) acc += tanhf(row[a] + shp[a]);
        #pragma unroll
        for (int o = 16; o; o >>= 1) acc += __shfl_xor_sync(0xffffffffu, acc, o);
        if (lane == 0) salpha[s] = acc;
    }
    __syncthreads();
    if (w == 0) {
        float v0 = salpha[lane], v1 = salpha[lane + 32];
        float m = fmaxf(v0, v1);
        #pragma unroll
        for (int o = 16; o; o >>= 1) m = fmaxf(m, __shfl_xor_sync(0xffffffffu, m, o));
        float e0 = expf(v0 - m), e1 = expf(v1 - m);
        float sum = e0 + e1;
        #pragma unroll
        for (int o = 16; o; o >>= 1) sum += __shfl_xor_sync(0xffffffffu, sum, o);
        float inv = 1.f / sum;
        salpha[lane] = e0 * inv; salpha[lane + 32] = e1 * inv;
    }
    __syncthreads();
    float a0 = 0.f, a1 = 0.f;
    for (int s = 0; s < Ss; s++) {
        float al = salpha[s];
        const float* eo = enc_out + ((size_t)b*Ss + s)*(2*Hh);
        a0 += al * eo[tid];
        a1 += al * eo[Hh + tid];
    }
    rnin[(size_t)b*RNK + Ee + tid]      = a0;
    rnin[(size_t)b*RNK + Ee + Hh + tid] = a1;

    __half h2, l2;
    h_split2(a0, h2, l2);
    catHi[(size_t)b*CAT + Dd + tid] = h2;
    catLo[(size_t)b*CAT + Dd + tid] = l2;
    h_split2(a1, h2, l2);
    catHi[(size_t)b*CAT + Dd + Hh + tid] = h2;
    catLo[(size_t)b*CAT + Dd + Hh + tid] = l2;

    int tk = (int)(0xFFFFFFFFu - (unsigned)(slots[b] & 0xFFFFFFFFull));
    float e = tab[(size_t)tk * Ee + tid];
    rnin[(size_t)b*RNK + tid] = e;
    h_split2(e, h2, l2);
    catHi[(size_t)b*CAT + Dd + 2*Hh + tid] = h2;
    catLo[(size_t)b*CAT + Dd + 2*Hh + tid] = l2;
}

__global__ void logsoftmax_kernel(float* __restrict__ out)
{
    int row = blockIdx.x, tid = threadIdx.x;
    int s = row & (Ss - 1);
    float* p = out + (size_t)row * Vv;
    if (s == 0) {
        float L = logf(expf(1.f) + (float)(Vv - 1));
        for (int v = tid; v < Vv; v += 256) p[v] = (v == 0 ? 1.f : 0.f) - L;
        return;
    }
    constexpr int PT = (Vv + 255) / 256;
    float regs[PT];
    float m = -INFINITY;
    #pragma unroll
    for (int i = 0; i < PT; i++) {
        int v = tid + i * 256;
        if (v < Vv) { regs[i] = p[v]; m = fmaxf(m, regs[i]); }
        else regs[i] = -INFINITY;
    }
    __shared__ float sm[256];
    sm[tid] = m; __syncthreads();
    for (int o = 128; o; o >>= 1) { if (tid < o) sm[tid] = fmaxf(sm[tid], sm[tid+o]); __syncthreads(); }
    m = sm[0]; __syncthreads();
    float sum = 0.f;
    #pragma unroll
    for (int i = 0; i < PT; i++) {
        int v = tid + i * 256;
        if (v < Vv) sum += expf(regs[i] - m);
    }
    sm[tid] = sum; __syncthreads();
    for (int o = 128; o; o >>= 1) { if (tid < o) sm[tid] += sm[tid+o]; __syncthreads(); }
    float ls = m + logf(sm[0]);
    #pragma unroll
    for (int i = 0; i < PT; i++) {
        int v = tid + i * 256;
        if (v < Vv) p[v] = regs[i] - ls;
    }
}

// ---------------- launch helpers ------------------------------------------
static inline dim3 gridL(int M, int N) { return dim3((N + 63) / 64, M / 128); }

extern "C" void kernel_launch(void* const* d_in, const int* in_sizes, int n_in,
                              void* d_out, int out_size)
{
    const int*   inp       = (const int*)  d_in[0];
    const float* emb_table = (const float*)d_in[1];
    const float* Wih_f     = (const float*)d_in[2];
    const float* Whh_f     = (const float*)d_in[3];
    const float* bih_f     = (const float*)d_in[4];
    const float* bhh_f     = (const float*)d_in[5];
    const float* Wih_b     = (const float*)d_in[6];
    const float* Whh_b     = (const float*)d_in[7];
    const float* bih_b     = (const float*)d_in[8];
    const float* bhh_b     = (const float*)d_in[9];
    const float* fc_W      = (const float*)d_in[10];
    const float* fc_b      = (const float*)d_in[11];
    const float* attn_W    = (const float*)d_in[12];
    const float* attn_b    = (const float*)d_in[13];
    const float* dec_Wih   = (const float*)d_in[14];
    const float* dec_Whh   = (const float*)d_in[15];
    const float* dec_bih   = (const float*)d_in[16];
    const float* dec_bhh   = (const float*)d_in[17];
    const float* out_W     = (const float*)d_in[18];
    const float* out_b     = (const float*)d_in[19];
    float* out = (float*)d_out;

    float* scr = nullptr;
    cudaGetSymbolAddress((void**)&scr, g_scratch);
    float* emb   = scr + OFF_EMB;
    float* xpf   = scr + OFF_XPF;
    float* xpb   = scr + OFF_XPB;
    float* enco  = scr + OFF_ENCO;
    float* encp  = scr + OFF_ENCP;
    float* hf0   = scr + OFF_HF0;
    float* hf1   = scr + OFF_HF1;
    float* hb0   = scr + OFF_HB0;
    float* hb1   = scr + OFF_HB1;
    float* hid0  = scr + OFF_HID0;
    float* hid1  = scr + OFF_HID1;
    float* fcin  = scr + OFF_FCIN;
    float* rnin  = scr + OFF_RNIN;
    float* attWT = scr + OFF_ATTWT;
    __half* catHi = (__half*)(scr + OFF_CATHI);
    __half* catLo = (__half*)(scr + OFF_CATLO);
    __half* Whi   = (__half*)(scr + OFF_WHI);
    __half* Wlo   = (__half*)(scr + OFF_WLO);
    unsigned long long* slots = (unsigned long long*)(scr + OFF_SLOT);

    // ---- init + embedding + one-time GEMMs + weight split ----
    init0_kernel<<<(Bb*Hh + 255)/256, 256>>>(hf0, hb0, slots);
    embed_kernel<<<Bb*Ss, 256>>>(inp, emb_table, emb);
    transpose_attw_kernel<<<Dd, Aa>>>(attn_W, attWT);
    split_w_kernel<<<(Vv*CAT + 255)/256, 256>>>(out_W, Whi, Wlo, Vv*CAT);
    gemmL<<<gridL(Bb*Ss, 3*Hh), 256>>>(emb, Ee, Wih_f, Ee, xpf, 3*Hh, bih_f, Bb*Ss, 3*Hh, Ee);
    gemmL<<<gridL(Bb*Ss, 3*Hh), 256>>>(emb, Ee, Wih_b, Ee, xpb, 3*Hh, bih_b, Bb*Ss, 3*Hh, Ee);

    // ---- encoder recurrence ----
    for (int t = 0; t < Ss; t++) {
        const float* hfi = (t & 1) ? hf1 : hf0;
        const float* hbi = (t & 1) ? hb1 : hb0;
        float* hfo = (t & 1) ? hf0 : hf1;
        float* hbo = (t & 1) ? hb0 : hb1;
        enc_step_kernel<<<dim3(8, 4, 2), 256>>>(hfi, hbi, hfo, hbo,
                                                Whh_f, Whh_b, bhh_f, bhh_b,
                                                xpf, xpb, enco, t);
    }

    // ---- decoder init ----
    concat_fc_kernel<<<Bb, 256>>>(hf0, hb0, fcin);
    gemm32t<<<dim3(Dd/32, Bb/32), 256>>>(fcin, 2*Hh, fc_W, 2*Hh, hid0, Dd, fc_b, Bb, Dd, 2*Hh);

    // ---- attention projection of enc_out (one-time) ----
    gemmL<<<gridL(Bb*Ss, Aa), 256>>>(enco, 2*Hh, attn_W + Dd, Dd + 2*Hh, encp, Aa, attn_b, Bb*Ss, Aa, 2*Hh);

    // ---- decoder steps (3 launches each) ----
    const dim3 gH((Vv + 63) / 64, Bb / 64);
    for (int t = 0; t < Ss - 1; t++) {
        const float* hin = (t & 1) ? hid1 : hid0;
        float*       hout = (t & 1) ? hid0 : hid1;
        attn_embed_kernel<<<Bb, 256>>>(encp, hin, attWT, enco, slots, emb_table,
                                       rnin, catHi, catLo);
        dec_fused_kernel<<<dim3(8, 4), 256>>>(rnin, hin, dec_Wih, dec_Whh,
                                              dec_bih, dec_bhh, hout,
                                              catHi, catLo, slots);
        gemmH<<<gH, 256>>>(catHi, catLo, Whi, Wlo, out_b,
                           out + (size_t)(t + 1) * Vv, Ss * Vv, slots);
    }

    // ---- final log-softmax ----
    logsoftmax_kernel<<<Bb*Ss, 256>>>(out);
}